// round 1
// baseline (speedup 1.0000x reference)
#include <cuda_runtime.h>
#include <math.h>

// ---------------------------------------------------------------------------
// Problem constants: B=2, S=2048, D=2048, H=16, DH=128
// ---------------------------------------------------------------------------
#define BB 2
#define SS 2048
#define DD 2048
#define HH 16
#define DHH 128
#define NTOK (BB * SS)          // 4096
#define QKV_N (3 * DD)          // 6144
#define LN_EPS 1e-5f

// Scratch (device globals; allocation forbidden)
__device__ float g_xln[(size_t)NTOK * DD];       // 33.5 MB
__device__ float g_qkv[(size_t)NTOK * QKV_N];    // 100.7 MB
__device__ float g_attn[(size_t)NTOK * DD];      // 33.5 MB

// ---------------------------------------------------------------------------
// LayerNorm: one block per token row, 256 threads, D=2048
// ---------------------------------------------------------------------------
__global__ __launch_bounds__(256) void ln_kernel(const float* __restrict__ x,
                                                 float* __restrict__ y) {
    __shared__ float red_s[8], red_ss[8];
    __shared__ float sh_mu, sh_rstd;
    const int row = blockIdx.x;
    const int tid = threadIdx.x;
    const float* xr = x + (size_t)row * DD;

    float4 a = *(const float4*)(xr + tid * 4);
    float4 b = *(const float4*)(xr + 1024 + tid * 4);
    float s  = a.x + a.y + a.z + a.w + b.x + b.y + b.z + b.w;
    float ss = a.x*a.x + a.y*a.y + a.z*a.z + a.w*a.w
             + b.x*b.x + b.y*b.y + b.z*b.z + b.w*b.w;

    #pragma unroll
    for (int o = 16; o > 0; o >>= 1) {
        s  += __shfl_xor_sync(0xffffffffu, s, o);
        ss += __shfl_xor_sync(0xffffffffu, ss, o);
    }
    const int wid = tid >> 5, lane = tid & 31;
    if (lane == 0) { red_s[wid] = s; red_ss[wid] = ss; }
    __syncthreads();
    if (tid == 0) {
        float S = 0.f, SSq = 0.f;
        #pragma unroll
        for (int w = 0; w < 8; w++) { S += red_s[w]; SSq += red_ss[w]; }
        float mu = S * (1.0f / DD);
        float var = SSq * (1.0f / DD) - mu * mu;
        sh_mu = mu;
        sh_rstd = rsqrtf(var + LN_EPS);
    }
    __syncthreads();
    const float mu = sh_mu, rstd = sh_rstd;
    float* yr = y + (size_t)row * DD;
    float4 oa, ob;
    oa.x = (a.x - mu) * rstd; oa.y = (a.y - mu) * rstd;
    oa.z = (a.z - mu) * rstd; oa.w = (a.w - mu) * rstd;
    ob.x = (b.x - mu) * rstd; ob.y = (b.y - mu) * rstd;
    ob.z = (b.z - mu) * rstd; ob.w = (b.w - mu) * rstd;
    *(float4*)(yr + tid * 4) = oa;
    *(float4*)(yr + 1024 + tid * 4) = ob;
}

// ---------------------------------------------------------------------------
// SGEMM: C[M,N] = A[M,K] @ B[K,N], all row-major, dims % 128 == 0, K % 8 == 0
// 128x128 block tile, BK=8, 256 threads, 8x8 per thread.
// ---------------------------------------------------------------------------
__global__ __launch_bounds__(256) void sgemm_kernel(const float* __restrict__ A,
                                                    const float* __restrict__ B,
                                                    float* __restrict__ C,
                                                    int M, int N, int K) {
    __shared__ float As[8][128];
    __shared__ float Bs[8][128];

    const int tid = threadIdx.x;
    const int bx = blockIdx.x;   // N tile
    const int by = blockIdx.y;   // M tile
    const int tx = tid & 15;
    const int ty = tid >> 4;

    const int aRow = tid >> 1;
    const int aCol = (tid & 1) * 4;
    const int bRow = tid >> 5;
    const int bCol = (tid & 31) * 4;

    const float* Ab = A + (size_t)(by * 128) * K;
    const float* Bb = B + (size_t)bx * 128;

    float acc[8][8];
    #pragma unroll
    for (int i = 0; i < 8; i++)
        #pragma unroll
        for (int j = 0; j < 8; j++) acc[i][j] = 0.f;

    for (int k0 = 0; k0 < K; k0 += 8) {
        float4 av = *(const float4*)(Ab + (size_t)aRow * K + k0 + aCol);
        As[aCol + 0][aRow] = av.x;
        As[aCol + 1][aRow] = av.y;
        As[aCol + 2][aRow] = av.z;
        As[aCol + 3][aRow] = av.w;
        float4 bv = *(const float4*)(Bb + (size_t)(k0 + bRow) * N + bCol);
        *(float4*)&Bs[bRow][bCol] = bv;
        __syncthreads();

        #pragma unroll
        for (int kk = 0; kk < 8; kk++) {
            float4 a0 = *(const float4*)&As[kk][ty * 8];
            float4 a1 = *(const float4*)&As[kk][ty * 8 + 4];
            float4 b0 = *(const float4*)&Bs[kk][tx * 8];
            float4 b1 = *(const float4*)&Bs[kk][tx * 8 + 4];
            float ar[8] = {a0.x,a0.y,a0.z,a0.w,a1.x,a1.y,a1.z,a1.w};
            float br[8] = {b0.x,b0.y,b0.z,b0.w,b1.x,b1.y,b1.z,b1.w};
            #pragma unroll
            for (int i = 0; i < 8; i++)
                #pragma unroll
                for (int j = 0; j < 8; j++)
                    acc[i][j] = fmaf(ar[i], br[j], acc[i][j]);
        }
        __syncthreads();
    }

    float* Cb = C + (size_t)(by * 128 + ty * 8) * N + bx * 128 + tx * 8;
    #pragma unroll
    for (int i = 0; i < 8; i++) {
        float4 v0 = {acc[i][0], acc[i][1], acc[i][2], acc[i][3]};
        float4 v1 = {acc[i][4], acc[i][5], acc[i][6], acc[i][7]};
        *(float4*)(Cb + (size_t)i * N) = v0;
        *(float4*)(Cb + (size_t)i * N + 4) = v1;
    }
}

// ---------------------------------------------------------------------------
// RoPE on q and k halves of qkv buffer, in place.
// positions == arange(S) broadcast per batch -> pos = token % S.
// ---------------------------------------------------------------------------
__global__ __launch_bounds__(256) void rope_kernel(float* __restrict__ qkv) {
    const int idx = blockIdx.x * blockDim.x + threadIdx.x;   // (token, head, pair)
    if (idx >= NTOK * HH * 64) return;
    const int d = idx & 63;
    const int h = (idx >> 6) & 15;
    const int t = idx >> 10;

    const float pos = (float)(t % SS);
    const float inv_freq = powf(10000.0f, -(float)d * (1.0f / 64.0f));
    const float ang = pos * inv_freq;
    const float c = cosf(ang), s = sinf(ang);

    float* q = qkv + (size_t)t * QKV_N + h * DHH;
    float x1 = q[d], x2 = q[d + 64];
    q[d]      = x1 * c - x2 * s;
    q[d + 64] = x2 * c + x1 * s;

    float* k = q + DD;
    x1 = k[d]; x2 = k[d + 64];
    k[d]      = x1 * c - x2 * s;
    k[d + 64] = x2 * c + x1 * s;
}

// ---------------------------------------------------------------------------
// Flash attention: per (q-block of 64, head, batch), causal, online softmax.
// 256 threads. Dynamic smem ~117KB.
// ---------------------------------------------------------------------------
#define QT 64
#define KT 64
#define QPAD 68      // QT + 4 (float4-aligned row stride for [d][m] tiles)
#define SCPAD 65

#define FLASH_SMEM_FLOATS (2 * DHH * QPAD + KT * DHH + QT * SCPAD + 3 * QT)
#define FLASH_SMEM_BYTES  (FLASH_SMEM_FLOATS * 4)

__global__ __launch_bounds__(256) void flash_kernel(const float* __restrict__ qkv,
                                                    float* __restrict__ attn) {
    extern __shared__ float sm[];
    float* Qs = sm;                        // [DHH][QPAD]
    float* Ks = Qs + DHH * QPAD;           // [DHH][QPAD]
    float* Vs = Ks + DHH * QPAD;           // [KT][DHH]
    float* Sc = Vs + KT * DHH;             // [QT][SCPAD]
    float* m_sh    = Sc + QT * SCPAD;      // [QT]
    float* l_sh    = m_sh + QT;            // [QT]
    float* corr_sh = l_sh + QT;            // [QT]

    const int qb = blockIdx.x;
    const int h  = blockIdx.y;
    const int b  = blockIdx.z;
    const int tid = threadIdx.x;
    const int tx = tid & 15;
    const int ty = tid >> 4;

    const float* qbase = qkv + (size_t)(b * SS) * QKV_N + h * DHH;
    const float* kbase = qbase + DD;
    const float* vbase = qbase + 2 * DD;

    // Load Q tile -> Qs[d][m]
    for (int i = tid; i < QT * (DHH / 4); i += 256) {
        int m  = i >> 5;
        int d4 = (i & 31) * 4;
        float4 v = *(const float4*)(qbase + (size_t)(qb * QT + m) * QKV_N + d4);
        Qs[(d4 + 0) * QPAD + m] = v.x;
        Qs[(d4 + 1) * QPAD + m] = v.y;
        Qs[(d4 + 2) * QPAD + m] = v.z;
        Qs[(d4 + 3) * QPAD + m] = v.w;
    }
    if (tid < QT) { m_sh[tid] = -INFINITY; l_sh[tid] = 0.f; }

    float accO[4][8];
    #pragma unroll
    for (int i = 0; i < 4; i++)
        #pragma unroll
        for (int j = 0; j < 8; j++) accO[i][j] = 0.f;

    const float scale = 0.088388347648318447f;   // 1/sqrt(128)

    for (int kt = 0; kt <= qb; kt++) {
        __syncthreads();   // protect Ks/Vs/Sc reuse (also orders Q load on iter 0)

        // Load K tile -> Ks[d][n], V tile -> Vs[n][d]
        for (int i = tid; i < KT * (DHH / 4); i += 256) {
            int n  = i >> 5;
            int d4 = (i & 31) * 4;
            const size_t grow = (size_t)(kt * KT + n) * QKV_N + d4;
            float4 kv = *(const float4*)(kbase + grow);
            Ks[(d4 + 0) * QPAD + n] = kv.x;
            Ks[(d4 + 1) * QPAD + n] = kv.y;
            Ks[(d4 + 2) * QPAD + n] = kv.z;
            Ks[(d4 + 3) * QPAD + n] = kv.w;
            float4 vv = *(const float4*)(vbase + grow);
            *(float4*)&Vs[n * DHH + d4] = vv;
        }
        __syncthreads();

        // Scores: 64x64 tile, each thread 4x4 (outer product over d)
        float acc[4][4];
        #pragma unroll
        for (int i = 0; i < 4; i++)
            #pragma unroll
            for (int j = 0; j < 4; j++) acc[i][j] = 0.f;

        #pragma unroll 4
        for (int d = 0; d < DHH; d++) {
            float4 a = *(const float4*)&Qs[d * QPAD + ty * 4];
            float4 bq = *(const float4*)&Ks[d * QPAD + tx * 4];
            float ar[4] = {a.x, a.y, a.z, a.w};
            float br[4] = {bq.x, bq.y, bq.z, bq.w};
            #pragma unroll
            for (int i = 0; i < 4; i++)
                #pragma unroll
                for (int j = 0; j < 4; j++)
                    acc[i][j] = fmaf(ar[i], br[j], acc[i][j]);
        }

        // Write scaled+masked scores
        const int qrow0 = qb * QT + ty * 4;
        const int kcol0 = kt * KT + tx * 4;
        #pragma unroll
        for (int i = 0; i < 4; i++)
            #pragma unroll
            for (int j = 0; j < 4; j++) {
                float sv = acc[i][j] * scale;
                if (kcol0 + j > qrow0 + i) sv = -1e30f;
                Sc[(ty * 4 + i) * SCPAD + tx * 4 + j] = sv;
            }
        __syncthreads();

        // Online softmax: 4 threads per row
        {
            const int r = tid >> 2, part = tid & 3;
            const int c0 = part * 16;
            float mold = m_sh[r];
            float mt = -1e30f;
            #pragma unroll
            for (int c = 0; c < 16; c++)
                mt = fmaxf(mt, Sc[r * SCPAD + c0 + c]);
            mt = fmaxf(mt, __shfl_xor_sync(0xffffffffu, mt, 1));
            mt = fmaxf(mt, __shfl_xor_sync(0xffffffffu, mt, 2));
            mt = fmaxf(mt, mold);
            float lsum = 0.f;
            #pragma unroll
            for (int c = 0; c < 16; c++) {
                float p = expf(Sc[r * SCPAD + c0 + c] - mt);
                Sc[r * SCPAD + c0 + c] = p;
                lsum += p;
            }
            lsum += __shfl_xor_sync(0xffffffffu, lsum, 1);
            lsum += __shfl_xor_sync(0xffffffffu, lsum, 2);
            if (part == 0) {
                float corr = expf(mold - mt);
                m_sh[r] = mt;
                corr_sh[r] = corr;
                l_sh[r] = l_sh[r] * corr + lsum;
            }
        }
        __syncthreads();

        // Rescale O and accumulate P @ V  (thread: rows ty*4+i, cols tx*8+j)
        #pragma unroll
        for (int i = 0; i < 4; i++) {
            float c = corr_sh[ty * 4 + i];
            #pragma unroll
            for (int j = 0; j < 8; j++) accO[i][j] *= c;
        }
        #pragma unroll 4
        for (int kk = 0; kk < KT; kk++) {
            float p0 = Sc[(ty * 4 + 0) * SCPAD + kk];
            float p1 = Sc[(ty * 4 + 1) * SCPAD + kk];
            float p2 = Sc[(ty * 4 + 2) * SCPAD + kk];
            float p3 = Sc[(ty * 4 + 3) * SCPAD + kk];
            float4 v0 = *(const float4*)&Vs[kk * DHH + tx * 8];
            float4 v1 = *(const float4*)&Vs[kk * DHH + tx * 8 + 4];
            float vr[8] = {v0.x, v0.y, v0.z, v0.w, v1.x, v1.y, v1.z, v1.w};
            float pr[4] = {p0, p1, p2, p3};
            #pragma unroll
            for (int i = 0; i < 4; i++)
                #pragma unroll
                for (int j = 0; j < 8; j++)
                    accO[i][j] = fmaf(pr[i], vr[j], accO[i][j]);
        }
    }

    // Epilogue: normalize and write attn[b, q, h, dh] -> (B,S,D) row-major
    #pragma unroll
    for (int i = 0; i < 4; i++) {
        float inv = 1.0f / l_sh[ty * 4 + i];
        float4 o0 = {accO[i][0] * inv, accO[i][1] * inv, accO[i][2] * inv, accO[i][3] * inv};
        float4 o1 = {accO[i][4] * inv, accO[i][5] * inv, accO[i][6] * inv, accO[i][7] * inv};
        float* dst = attn + (size_t)(b * SS + qb * QT + ty * 4 + i) * DD + h * DHH + tx * 8;
        *(float4*)dst = o0;
        *(float4*)(dst + 4) = o1;
    }
}

// ---------------------------------------------------------------------------
// kernel_launch: inputs = [positions, hidden_states, w_qkv, w_out]
// ---------------------------------------------------------------------------
extern "C" void kernel_launch(void* const* d_in, const int* in_sizes, int n_in,
                              void* d_out, int out_size) {
    const float* hidden = (const float*)d_in[1];
    const float* w_qkv  = (const float*)d_in[2];
    const float* w_out  = (const float*)d_in[3];
    float* out = (float*)d_out;

    float *xln, *qkv, *attn;
    cudaGetSymbolAddress((void**)&xln,  g_xln);
    cudaGetSymbolAddress((void**)&qkv,  g_qkv);
    cudaGetSymbolAddress((void**)&attn, g_attn);

    // 1) LayerNorm
    ln_kernel<<<NTOK, 256>>>(hidden, xln);

    // 2) QKV projection: [4096,2048] @ [2048,6144]
    sgemm_kernel<<<dim3(QKV_N / 128, NTOK / 128), 256>>>(xln, w_qkv, qkv,
                                                         NTOK, QKV_N, DD);

    // 3) RoPE on q,k
    rope_kernel<<<(NTOK * HH * 64 + 255) / 256, 256>>>(qkv);

    // 4) Causal flash attention
    cudaFuncSetAttribute(flash_kernel, cudaFuncAttributeMaxDynamicSharedMemorySize,
                         FLASH_SMEM_BYTES);
    flash_kernel<<<dim3(SS / QT, HH, BB), 256, FLASH_SMEM_BYTES>>>(qkv, attn);

    // 5) Output projection: [4096,2048] @ [2048,2048]
    sgemm_kernel<<<dim3(DD / 128, NTOK / 128), 256>>>(attn, w_out, out,
                                                      NTOK, DD, DD);
}

// round 3
// speedup vs baseline: 1.6363x; 1.6363x over previous
#include <cuda_runtime.h>
#include <cuda_bf16.h>
#include <math.h>
#include <cstdint>

// ---------------------------------------------------------------------------
// Problem constants: B=2, S=2048, D=2048, H=16, DH=128
// ---------------------------------------------------------------------------
#define BB 2
#define SS 2048
#define DD 2048
#define HH 16
#define DHH 128
#define NTOK (BB * SS)          // 4096
#define QKV_N (3 * DD)          // 6144
#define LN_EPS 1e-5f

// ---------------------------------------------------------------------------
// Scratch (device globals; allocation forbidden)
// ---------------------------------------------------------------------------
__device__ __nv_bfloat16 g_xln_hi[(size_t)NTOK * DD];
__device__ __nv_bfloat16 g_xln_lo[(size_t)NTOK * DD];
__device__ float         g_qkv[(size_t)NTOK * QKV_N];     // 100.7 MB
__device__ __nv_bfloat16 g_wqkvT_hi[(size_t)QKV_N * DD];
__device__ __nv_bfloat16 g_wqkvT_lo[(size_t)QKV_N * DD];
__device__ __nv_bfloat16 g_woutT_hi[(size_t)DD * DD];
__device__ __nv_bfloat16 g_woutT_lo[(size_t)DD * DD];
__device__ __nv_bfloat16 g_attn_hi[(size_t)NTOK * DD];
__device__ __nv_bfloat16 g_attn_lo[(size_t)NTOK * DD];

// ---------------------------------------------------------------------------
// helpers
// ---------------------------------------------------------------------------
__device__ __forceinline__ uint32_t smem_u32(const void* p) {
    uint32_t a;
    asm("{ .reg .u64 t; cvta.to.shared.u64 t, %1; cvt.u32.u64 %0, t; }"
        : "=r"(a) : "l"(p));
    return a;
}

__device__ __forceinline__ void cpa16(uint32_t dst, const void* src) {
    asm volatile("cp.async.cg.shared.global [%0], [%1], 16;" :: "r"(dst), "l"(src) : "memory");
}
#define CP_COMMIT() asm volatile("cp.async.commit_group;" ::: "memory")
#define CP_WAIT1()  asm volatile("cp.async.wait_group 1;" ::: "memory")
#define CP_WAIT0()  asm volatile("cp.async.wait_group 0;" ::: "memory")

__device__ __forceinline__ void mma_bf16(float* c, const uint32_t* a, const uint32_t* b) {
    asm volatile(
        "mma.sync.aligned.m16n8k16.row.col.f32.bf16.bf16.f32 "
        "{%0,%1,%2,%3}, {%4,%5,%6,%7}, {%8,%9}, {%0,%1,%2,%3};"
        : "+f"(c[0]), "+f"(c[1]), "+f"(c[2]), "+f"(c[3])
        : "r"(a[0]), "r"(a[1]), "r"(a[2]), "r"(a[3]), "r"(b[0]), "r"(b[1]));
}

__device__ __forceinline__ void split2(float v, __nv_bfloat16& h, __nv_bfloat16& l) {
    h = __float2bfloat16(v);
    l = __float2bfloat16(v - __bfloat162float(h));
}

// ---------------------------------------------------------------------------
// LayerNorm -> bf16 hi/lo split outputs
// ---------------------------------------------------------------------------
__global__ __launch_bounds__(256) void ln_kernel(const float* __restrict__ x,
                                                 __nv_bfloat16* __restrict__ yh,
                                                 __nv_bfloat16* __restrict__ yl) {
    __shared__ float red_s[8], red_ss[8];
    __shared__ float sh_mu, sh_rstd;
    const int row = blockIdx.x;
    const int tid = threadIdx.x;
    const float* xr = x + (size_t)row * DD;

    float4 a = *(const float4*)(xr + tid * 4);
    float4 b = *(const float4*)(xr + 1024 + tid * 4);
    float s  = a.x + a.y + a.z + a.w + b.x + b.y + b.z + b.w;
    float ss = a.x*a.x + a.y*a.y + a.z*a.z + a.w*a.w
             + b.x*b.x + b.y*b.y + b.z*b.z + b.w*b.w;
    #pragma unroll
    for (int o = 16; o > 0; o >>= 1) {
        s  += __shfl_xor_sync(0xffffffffu, s, o);
        ss += __shfl_xor_sync(0xffffffffu, ss, o);
    }
    const int wid = tid >> 5, lane = tid & 31;
    if (lane == 0) { red_s[wid] = s; red_ss[wid] = ss; }
    __syncthreads();
    if (tid == 0) {
        float S = 0.f, SSq = 0.f;
        #pragma unroll
        for (int w = 0; w < 8; w++) { S += red_s[w]; SSq += red_ss[w]; }
        float mu = S * (1.0f / DD);
        float var = SSq * (1.0f / DD) - mu * mu;
        sh_mu = mu;
        sh_rstd = rsqrtf(var + LN_EPS);
    }
    __syncthreads();
    const float mu = sh_mu, rstd = sh_rstd;
    float va[8] = {a.x, a.y, a.z, a.w, b.x, b.y, b.z, b.w};
    #pragma unroll
    for (int e = 0; e < 8; e++) {
        float v = (va[e] - mu) * rstd;
        __nv_bfloat16 h, l;
        split2(v, h, l);
        size_t col = (e < 4) ? (tid * 4 + e) : (1024 + tid * 4 + e - 4);
        yh[(size_t)row * DD + col] = h;
        yl[(size_t)row * DD + col] = l;
    }
}

// ---------------------------------------------------------------------------
// Transpose + split: W[K][N] fp32 -> hi/lo bf16 [N][K]
// ---------------------------------------------------------------------------
__global__ __launch_bounds__(256) void transpose_split(const float* __restrict__ W,
                                                       __nv_bfloat16* __restrict__ hi,
                                                       __nv_bfloat16* __restrict__ lo,
                                                       int K, int N) {
    __shared__ float t[32][33];
    int n = blockIdx.x * 32 + threadIdx.x;
    int k = blockIdx.y * 32 + threadIdx.y;
    #pragma unroll
    for (int i = 0; i < 4; i++)
        t[threadIdx.y + 8 * i][threadIdx.x] = W[(size_t)(k + 8 * i) * N + n];
    __syncthreads();
    int ko = blockIdx.y * 32 + threadIdx.x;
    int no = blockIdx.x * 32 + threadIdx.y;
    #pragma unroll
    for (int i = 0; i < 4; i++) {
        float v = t[threadIdx.x][threadIdx.y + 8 * i];
        __nv_bfloat16 h, l;
        split2(v, h, l);
        size_t o = (size_t)(no + 8 * i) * K + ko;
        hi[o] = h;
        lo[o] = l;
    }
}

// ---------------------------------------------------------------------------
// mma.sync split-bf16 GEMM: C[M,N] fp32 = (Ahi+Alo)[M,K] @ (Bhi+Blo)[N,K]^T
// CTA tile 128x128, BK=32, 8 warps (4x2), warp tile 32x64.
// Smem rows padded to 80B for conflict-free b32 fragment loads.
// ---------------------------------------------------------------------------
#define BM 128
#define BN 128
#define BKC 32
#define ROWB 80                       // padded row bytes (32 bf16 = 64B data)
#define TILE_B (128 * ROWB)           // 10240 per operand tile
#define STAGE_B (4 * TILE_B)          // Ah, Al, Bh, Bl = 40960
#define GEMM_SMEM (2 * STAGE_B)       // 81920

__global__ __launch_bounds__(256, 1) void gemm_mma(
    const __nv_bfloat16* __restrict__ Ahi, const __nv_bfloat16* __restrict__ Alo,
    const __nv_bfloat16* __restrict__ Bhi, const __nv_bfloat16* __restrict__ Blo,
    float* __restrict__ C, int M, int N, int K)
{
    extern __shared__ __align__(16) char smem[];
    const uint32_t sb = smem_u32(smem);
    const int tid = threadIdx.x;
    const int wid = tid >> 5;
    const int lane = tid & 31;
    const int m0 = blockIdx.y * BM;
    const int n0 = blockIdx.x * BN;
    const int wm = (wid & 3) * 32;        // warp m offset in CTA tile
    const int wn = (wid >> 2) * 64;       // warp n offset

    const __nv_bfloat16* srcs[4] = {Ahi, Alo, Bhi, Blo};

    // acc[mi][ni][4]
    float acc[2][8][4];
    #pragma unroll
    for (int mi = 0; mi < 2; mi++)
        #pragma unroll
        for (int ni = 0; ni < 8; ni++)
            #pragma unroll
            for (int e = 0; e < 4; e++) acc[mi][ni][e] = 0.f;

    auto fill = [&](int stage, int k0) {
        const uint32_t sbase = sb + stage * STAGE_B;
        #pragma unroll
        for (int it = 0; it < 8; it++) {
            int i = it * 256 + tid;               // 2048 chunks
            int op = i >> 9;                      // 0..3
            int r  = (i >> 2) & 127;
            int c  = i & 3;
            int rowg = (op < 2) ? (m0 + r) : (n0 + r);
            const __nv_bfloat16* src = srcs[op] + (size_t)rowg * K + k0 + c * 8;
            uint32_t dst = sbase + op * TILE_B + r * ROWB + c * 16;
            cpa16(dst, src);
        }
        CP_COMMIT();
    };

    const int nch = K / BKC;
    fill(0, 0);
    fill(1, BKC);

    const int r4 = lane >> 2;      // 0..7
    const int k4 = lane & 3;       // 0..3

    for (int c = 0; c < nch; c++) {
        const int s = c & 1;
        if (c + 1 < nch) CP_WAIT1(); else CP_WAIT0();
        __syncthreads();

        const uint32_t sbase = sb + s * STAGE_B;
        const uint32_t aHi = sbase;
        const uint32_t aLo = sbase + TILE_B;
        const uint32_t bHi = sbase + 2 * TILE_B;
        const uint32_t bLo = sbase + 3 * TILE_B;

        #pragma unroll
        for (int ks = 0; ks < 2; ks++) {
            const uint32_t kb = ks * 32 + k4 * 4;     // byte offset in row

            uint32_t ah[2][4], al[2][4], bh[8][2], bl[8][2];
            #pragma unroll
            for (int mi = 0; mi < 2; mi++) {
                uint32_t ro = (wm + mi * 16 + r4) * ROWB + kb;
                asm volatile("ld.shared.b32 %0, [%1];" : "=r"(ah[mi][0]) : "r"(aHi + ro));
                asm volatile("ld.shared.b32 %0, [%1];" : "=r"(ah[mi][1]) : "r"(aHi + ro + 8 * ROWB));
                asm volatile("ld.shared.b32 %0, [%1];" : "=r"(ah[mi][2]) : "r"(aHi + ro + 16));
                asm volatile("ld.shared.b32 %0, [%1];" : "=r"(ah[mi][3]) : "r"(aHi + ro + 8 * ROWB + 16));
                asm volatile("ld.shared.b32 %0, [%1];" : "=r"(al[mi][0]) : "r"(aLo + ro));
                asm volatile("ld.shared.b32 %0, [%1];" : "=r"(al[mi][1]) : "r"(aLo + ro + 8 * ROWB));
                asm volatile("ld.shared.b32 %0, [%1];" : "=r"(al[mi][2]) : "r"(aLo + ro + 16));
                asm volatile("ld.shared.b32 %0, [%1];" : "=r"(al[mi][3]) : "r"(aLo + ro + 8 * ROWB + 16));
            }
            #pragma unroll
            for (int ni = 0; ni < 8; ni++) {
                uint32_t ro = (wn + ni * 8 + r4) * ROWB + kb;
                asm volatile("ld.shared.b32 %0, [%1];" : "=r"(bh[ni][0]) : "r"(bHi + ro));
                asm volatile("ld.shared.b32 %0, [%1];" : "=r"(bh[ni][1]) : "r"(bHi + ro + 16));
                asm volatile("ld.shared.b32 %0, [%1];" : "=r"(bl[ni][0]) : "r"(bLo + ro));
                asm volatile("ld.shared.b32 %0, [%1];" : "=r"(bl[ni][1]) : "r"(bLo + ro + 16));
            }

            #pragma unroll
            for (int mi = 0; mi < 2; mi++)
                #pragma unroll
                for (int ni = 0; ni < 8; ni++) {
                    mma_bf16(acc[mi][ni], ah[mi], bh[ni]);
                    mma_bf16(acc[mi][ni], ah[mi], bl[ni]);
                    mma_bf16(acc[mi][ni], al[mi], bh[ni]);
                }
        }

        __syncthreads();
        if (c + 2 < nch) fill(s, (c + 2) * BKC);
    }

    // epilogue: c0 (r, cc), c1 (r, cc+1), c2 (r+8, cc), c3 (r+8, cc+1)
    #pragma unroll
    for (int mi = 0; mi < 2; mi++) {
        int r0 = m0 + wm + mi * 16 + r4;
        #pragma unroll
        for (int ni = 0; ni < 8; ni++) {
            int cc = n0 + wn + ni * 8 + k4 * 2;
            float2 v0 = {acc[mi][ni][0], acc[mi][ni][1]};
            float2 v1 = {acc[mi][ni][2], acc[mi][ni][3]};
            *(float2*)(C + (size_t)r0 * N + cc) = v0;
            *(float2*)(C + (size_t)(r0 + 8) * N + cc) = v1;
        }
    }
}

// ---------------------------------------------------------------------------
// RoPE (in place, fp32 qkv).  positions = arange(S) per batch.
// ---------------------------------------------------------------------------
__global__ __launch_bounds__(256) void rope_kernel(float* __restrict__ qkv) {
    const int idx = blockIdx.x * blockDim.x + threadIdx.x;
    if (idx >= NTOK * HH * 64) return;
    const int d = idx & 63;
    const int h = (idx >> 6) & 15;
    const int t = idx >> 10;

    const float pos = (float)(t % SS);
    const float inv_freq = powf(10000.0f, -(float)d * (1.0f / 64.0f));
    const float ang = pos * inv_freq;
    const float c = cosf(ang), s = sinf(ang);

    float* q = qkv + (size_t)t * QKV_N + h * DHH;
    float x1 = q[d], x2 = q[d + 64];
    q[d]      = x1 * c - x2 * s;
    q[d + 64] = x2 * c + x1 * s;

    float* k = q + DD;
    x1 = k[d]; x2 = k[d + 64];
    k[d]      = x1 * c - x2 * s;
    k[d + 64] = x2 * c + x1 * s;
}

// ---------------------------------------------------------------------------
// Flash attention (fp32), outputs split bf16 hi/lo for the out-proj GEMM.
// ---------------------------------------------------------------------------
#define QT 64
#define KT 64
#define QPAD 68
#define SCPAD 65
#define FLASH_SMEM_FLOATS (2 * DHH * QPAD + KT * DHH + QT * SCPAD + 3 * QT)
#define FLASH_SMEM_BYTES  (FLASH_SMEM_FLOATS * 4)

__global__ __launch_bounds__(256) void flash_kernel(const float* __restrict__ qkv,
                                                    __nv_bfloat16* __restrict__ attn_hi,
                                                    __nv_bfloat16* __restrict__ attn_lo) {
    extern __shared__ float sm[];
    float* Qs = sm;
    float* Ks = Qs + DHH * QPAD;
    float* Vs = Ks + DHH * QPAD;
    float* Sc = Vs + KT * DHH;
    float* m_sh    = Sc + QT * SCPAD;
    float* l_sh    = m_sh + QT;
    float* corr_sh = l_sh + QT;

    const int qb = blockIdx.x;
    const int h  = blockIdx.y;
    const int b  = blockIdx.z;
    const int tid = threadIdx.x;
    const int tx = tid & 15;
    const int ty = tid >> 4;

    const float* qbase = qkv + (size_t)(b * SS) * QKV_N + h * DHH;
    const float* kbase = qbase + DD;
    const float* vbase = qbase + 2 * DD;

    for (int i = tid; i < QT * (DHH / 4); i += 256) {
        int m  = i >> 5;
        int d4 = (i & 31) * 4;
        float4 v = *(const float4*)(qbase + (size_t)(qb * QT + m) * QKV_N + d4);
        Qs[(d4 + 0) * QPAD + m] = v.x;
        Qs[(d4 + 1) * QPAD + m] = v.y;
        Qs[(d4 + 2) * QPAD + m] = v.z;
        Qs[(d4 + 3) * QPAD + m] = v.w;
    }
    if (tid < QT) { m_sh[tid] = -INFINITY; l_sh[tid] = 0.f; }

    float accO[4][8];
    #pragma unroll
    for (int i = 0; i < 4; i++)
        #pragma unroll
        for (int j = 0; j < 8; j++) accO[i][j] = 0.f;

    const float scale = 0.088388347648318447f;

    for (int kt = 0; kt <= qb; kt++) {
        __syncthreads();
        for (int i = tid; i < KT * (DHH / 4); i += 256) {
            int n  = i >> 5;
            int d4 = (i & 31) * 4;
            const size_t grow = (size_t)(kt * KT + n) * QKV_N + d4;
            float4 kv = *(const float4*)(kbase + grow);
            Ks[(d4 + 0) * QPAD + n] = kv.x;
            Ks[(d4 + 1) * QPAD + n] = kv.y;
            Ks[(d4 + 2) * QPAD + n] = kv.z;
            Ks[(d4 + 3) * QPAD + n] = kv.w;
            float4 vv = *(const float4*)(vbase + grow);
            *(float4*)&Vs[n * DHH + d4] = vv;
        }
        __syncthreads();

        float acc[4][4];
        #pragma unroll
        for (int i = 0; i < 4; i++)
            #pragma unroll
            for (int j = 0; j < 4; j++) acc[i][j] = 0.f;

        #pragma unroll 4
        for (int d = 0; d < DHH; d++) {
            float4 a = *(const float4*)&Qs[d * QPAD + ty * 4];
            float4 bq = *(const float4*)&Ks[d * QPAD + tx * 4];
            float ar[4] = {a.x, a.y, a.z, a.w};
            float br[4] = {bq.x, bq.y, bq.z, bq.w};
            #pragma unroll
            for (int i = 0; i < 4; i++)
                #pragma unroll
                for (int j = 0; j < 4; j++)
                    acc[i][j] = fmaf(ar[i], br[j], acc[i][j]);
        }

        const int qrow0 = qb * QT + ty * 4;
        const int kcol0 = kt * KT + tx * 4;
        #pragma unroll
        for (int i = 0; i < 4; i++)
            #pragma unroll
            for (int j = 0; j < 4; j++) {
                float sv = acc[i][j] * scale;
                if (kcol0 + j > qrow0 + i) sv = -1e30f;
                Sc[(ty * 4 + i) * SCPAD + tx * 4 + j] = sv;
            }
        __syncthreads();

        {
            const int r = tid >> 2, part = tid & 3;
            const int c0 = part * 16;
            float mold = m_sh[r];
            float mt = -1e30f;
            #pragma unroll
            for (int c = 0; c < 16; c++)
                mt = fmaxf(mt, Sc[r * SCPAD + c0 + c]);
            mt = fmaxf(mt, __shfl_xor_sync(0xffffffffu, mt, 1));
            mt = fmaxf(mt, __shfl_xor_sync(0xffffffffu, mt, 2));
            mt = fmaxf(mt, mold);
            float lsum = 0.f;
            #pragma unroll
            for (int c = 0; c < 16; c++) {
                float p = expf(Sc[r * SCPAD + c0 + c] - mt);
                Sc[r * SCPAD + c0 + c] = p;
                lsum += p;
            }
            lsum += __shfl_xor_sync(0xffffffffu, lsum, 1);
            lsum += __shfl_xor_sync(0xffffffffu, lsum, 2);
            if (part == 0) {
                float corr = expf(mold - mt);
                m_sh[r] = mt;
                corr_sh[r] = corr;
                l_sh[r] = l_sh[r] * corr + lsum;
            }
        }
        __syncthreads();

        #pragma unroll
        for (int i = 0; i < 4; i++) {
            float c = corr_sh[ty * 4 + i];
            #pragma unroll
            for (int j = 0; j < 8; j++) accO[i][j] *= c;
        }
        #pragma unroll 4
        for (int kk = 0; kk < KT; kk++) {
            float p0 = Sc[(ty * 4 + 0) * SCPAD + kk];
            float p1 = Sc[(ty * 4 + 1) * SCPAD + kk];
            float p2 = Sc[(ty * 4 + 2) * SCPAD + kk];
            float p3 = Sc[(ty * 4 + 3) * SCPAD + kk];
            float4 v0 = *(const float4*)&Vs[kk * DHH + tx * 8];
            float4 v1 = *(const float4*)&Vs[kk * DHH + tx * 8 + 4];
            float vr[8] = {v0.x, v0.y, v0.z, v0.w, v1.x, v1.y, v1.z, v1.w};
            float pr[4] = {p0, p1, p2, p3};
            #pragma unroll
            for (int i = 0; i < 4; i++)
                #pragma unroll
                for (int j = 0; j < 8; j++)
                    accO[i][j] = fmaf(pr[i], vr[j], accO[i][j]);
        }
    }

    #pragma unroll
    for (int i = 0; i < 4; i++) {
        float inv = 1.0f / l_sh[ty * 4 + i];
        size_t base = (size_t)(b * SS + qb * QT + ty * 4 + i) * DD + h * DHH + tx * 8;
        #pragma unroll
        for (int j = 0; j < 8; j++) {
            float v = accO[i][j] * inv;
            __nv_bfloat16 hh, ll;
            split2(v, hh, ll);
            attn_hi[base + j] = hh;
            attn_lo[base + j] = ll;
        }
    }
}

// ---------------------------------------------------------------------------
// kernel_launch: inputs = [positions, hidden_states, w_qkv, w_out]
// ---------------------------------------------------------------------------
extern "C" void kernel_launch(void* const* d_in, const int* in_sizes, int n_in,
                              void* d_out, int out_size) {
    const float* hidden = (const float*)d_in[1];
    const float* w_qkv  = (const float*)d_in[2];
    const float* w_out  = (const float*)d_in[3];
    float* out = (float*)d_out;

    __nv_bfloat16 *xh, *xl, *wqh, *wql, *woh, *wol, *ah, *al;
    float* qkv;
    cudaGetSymbolAddress((void**)&xh,  g_xln_hi);
    cudaGetSymbolAddress((void**)&xl,  g_xln_lo);
    cudaGetSymbolAddress((void**)&qkv, g_qkv);
    cudaGetSymbolAddress((void**)&wqh, g_wqkvT_hi);
    cudaGetSymbolAddress((void**)&wql, g_wqkvT_lo);
    cudaGetSymbolAddress((void**)&woh, g_woutT_hi);
    cudaGetSymbolAddress((void**)&wol, g_woutT_lo);
    cudaGetSymbolAddress((void**)&ah,  g_attn_hi);
    cudaGetSymbolAddress((void**)&al,  g_attn_lo);

    // 1) LayerNorm -> split bf16
    ln_kernel<<<NTOK, 256>>>(hidden, xh, xl);

    // 2) Weight transpose+split
    dim3 tb(32, 8);
    transpose_split<<<dim3(QKV_N / 32, DD / 32), tb>>>(w_qkv, wqh, wql, DD, QKV_N);
    transpose_split<<<dim3(DD / 32, DD / 32), tb>>>(w_out, woh, wol, DD, DD);

    // 3) QKV projection (tensor cores via mma.sync)
    cudaFuncSetAttribute(gemm_mma, cudaFuncAttributeMaxDynamicSharedMemorySize, GEMM_SMEM);
    gemm_mma<<<dim3(QKV_N / BN, NTOK / BM), 256, GEMM_SMEM>>>(
        xh, xl, wqh, wql, qkv, NTOK, QKV_N, DD);

    // 4) RoPE
    rope_kernel<<<(NTOK * HH * 64 + 255) / 256, 256>>>(qkv);

    // 5) Causal flash attention (fp32) -> split bf16
    cudaFuncSetAttribute(flash_kernel, cudaFuncAttributeMaxDynamicSharedMemorySize,
                         FLASH_SMEM_BYTES);
    flash_kernel<<<dim3(SS / QT, HH, BB), 256, FLASH_SMEM_BYTES>>>(qkv, ah, al);

    // 6) Output projection (tensor cores via mma.sync)
    gemm_mma<<<dim3(DD / BN, NTOK / BM), 256, GEMM_SMEM>>>(
        ah, al, woh, wol, out, NTOK, DD, DD);
}

// round 4
// speedup vs baseline: 2.3868x; 1.4587x over previous
#include <cuda_runtime.h>
#include <cuda_bf16.h>
#include <math.h>
#include <cstdint>

// ---------------------------------------------------------------------------
// Problem constants: B=2, S=2048, D=2048, H=16, DH=128
// ---------------------------------------------------------------------------
#define BB 2
#define SS 2048
#define DD 2048
#define HH 16
#define DHH 128
#define NTOK (BB * SS)          // 4096
#define QKV_N (3 * DD)          // 6144
#define LN_EPS 1e-5f

// ---------------------------------------------------------------------------
// Scratch (device globals; allocation forbidden)
// ---------------------------------------------------------------------------
__device__ __nv_bfloat16 g_xln_hi[(size_t)NTOK * DD];
__device__ __nv_bfloat16 g_xln_lo[(size_t)NTOK * DD];
__device__ float         g_qkv[(size_t)NTOK * QKV_N];     // 100.7 MB
__device__ __nv_bfloat16 g_wqkvT_hi[(size_t)QKV_N * DD];
__device__ __nv_bfloat16 g_wqkvT_lo[(size_t)QKV_N * DD];
__device__ __nv_bfloat16 g_woutT_hi[(size_t)DD * DD];
__device__ __nv_bfloat16 g_woutT_lo[(size_t)DD * DD];
__device__ __nv_bfloat16 g_attn_hi[(size_t)NTOK * DD];
__device__ __nv_bfloat16 g_attn_lo[(size_t)NTOK * DD];

// ---------------------------------------------------------------------------
// helpers
// ---------------------------------------------------------------------------
__device__ __forceinline__ uint32_t smem_u32(const void* p) {
    uint32_t a;
    asm("{ .reg .u64 t; cvta.to.shared.u64 t, %1; cvt.u32.u64 %0, t; }"
        : "=r"(a) : "l"(p));
    return a;
}

__device__ __forceinline__ void cpa16(uint32_t dst, const void* src) {
    asm volatile("cp.async.cg.shared.global [%0], [%1], 16;" :: "r"(dst), "l"(src) : "memory");
}
#define CP_COMMIT() asm volatile("cp.async.commit_group;" ::: "memory")
#define CP_WAIT1()  asm volatile("cp.async.wait_group 1;" ::: "memory")
#define CP_WAIT0()  asm volatile("cp.async.wait_group 0;" ::: "memory")

__device__ __forceinline__ void mma_bf16(float* c, const uint32_t* a, const uint32_t* b) {
    asm volatile(
        "mma.sync.aligned.m16n8k16.row.col.f32.bf16.bf16.f32 "
        "{%0,%1,%2,%3}, {%4,%5,%6,%7}, {%8,%9}, {%0,%1,%2,%3};"
        : "+f"(c[0]), "+f"(c[1]), "+f"(c[2]), "+f"(c[3])
        : "r"(a[0]), "r"(a[1]), "r"(a[2]), "r"(a[3]), "r"(b[0]), "r"(b[1]));
}

__device__ __forceinline__ void split2(float v, __nv_bfloat16& h, __nv_bfloat16& l) {
    h = __float2bfloat16(v);
    l = __float2bfloat16(v - __bfloat162float(h));
}

__device__ __forceinline__ uint32_t packbf(__nv_bfloat16 a, __nv_bfloat16 b) {
    __nv_bfloat162 t(a, b);   // a = low element
    return *(uint32_t*)&t;
}

// ---------------------------------------------------------------------------
// LayerNorm -> bf16 hi/lo split outputs
// ---------------------------------------------------------------------------
__global__ __launch_bounds__(256) void ln_kernel(const float* __restrict__ x,
                                                 __nv_bfloat16* __restrict__ yh,
                                                 __nv_bfloat16* __restrict__ yl) {
    __shared__ float red_s[8], red_ss[8];
    __shared__ float sh_mu, sh_rstd;
    const int row = blockIdx.x;
    const int tid = threadIdx.x;
    const float* xr = x + (size_t)row * DD;

    float4 a = *(const float4*)(xr + tid * 4);
    float4 b = *(const float4*)(xr + 1024 + tid * 4);
    float s  = a.x + a.y + a.z + a.w + b.x + b.y + b.z + b.w;
    float ss = a.x*a.x + a.y*a.y + a.z*a.z + a.w*a.w
             + b.x*b.x + b.y*b.y + b.z*b.z + b.w*b.w;
    #pragma unroll
    for (int o = 16; o > 0; o >>= 1) {
        s  += __shfl_xor_sync(0xffffffffu, s, o);
        ss += __shfl_xor_sync(0xffffffffu, ss, o);
    }
    const int wid = tid >> 5, lane = tid & 31;
    if (lane == 0) { red_s[wid] = s; red_ss[wid] = ss; }
    __syncthreads();
    if (tid == 0) {
        float S = 0.f, SSq = 0.f;
        #pragma unroll
        for (int w = 0; w < 8; w++) { S += red_s[w]; SSq += red_ss[w]; }
        float mu = S * (1.0f / DD);
        float var = SSq * (1.0f / DD) - mu * mu;
        sh_mu = mu;
        sh_rstd = rsqrtf(var + LN_EPS);
    }
    __syncthreads();
    const float mu = sh_mu, rstd = sh_rstd;
    float va[8] = {a.x, a.y, a.z, a.w, b.x, b.y, b.z, b.w};
    #pragma unroll
    for (int e = 0; e < 8; e++) {
        float v = (va[e] - mu) * rstd;
        __nv_bfloat16 h, l;
        split2(v, h, l);
        size_t col = (e < 4) ? (tid * 4 + e) : (1024 + tid * 4 + e - 4);
        yh[(size_t)row * DD + col] = h;
        yl[(size_t)row * DD + col] = l;
    }
}

// ---------------------------------------------------------------------------
// Transpose + split: W[K][N] fp32 -> hi/lo bf16 [N][K]
// ---------------------------------------------------------------------------
__global__ __launch_bounds__(256) void transpose_split(const float* __restrict__ W,
                                                       __nv_bfloat16* __restrict__ hi,
                                                       __nv_bfloat16* __restrict__ lo,
                                                       int K, int N) {
    __shared__ float t[32][33];
    int n = blockIdx.x * 32 + threadIdx.x;
    int k = blockIdx.y * 32 + threadIdx.y;
    #pragma unroll
    for (int i = 0; i < 4; i++)
        t[threadIdx.y + 8 * i][threadIdx.x] = W[(size_t)(k + 8 * i) * N + n];
    __syncthreads();
    int ko = blockIdx.y * 32 + threadIdx.x;
    int no = blockIdx.x * 32 + threadIdx.y;
    #pragma unroll
    for (int i = 0; i < 4; i++) {
        float v = t[threadIdx.x][threadIdx.y + 8 * i];
        __nv_bfloat16 h, l;
        split2(v, h, l);
        size_t o = (size_t)(no + 8 * i) * K + ko;
        hi[o] = h;
        lo[o] = l;
    }
}

// ---------------------------------------------------------------------------
// mma.sync split-bf16 GEMM (unchanged from round 3 — proven)
// ---------------------------------------------------------------------------
#define BM 128
#define BN 128
#define BKC 32
#define ROWB 80
#define TILE_B (128 * ROWB)
#define STAGE_B (4 * TILE_B)
#define GEMM_SMEM (2 * STAGE_B)

__global__ __launch_bounds__(256, 1) void gemm_mma(
    const __nv_bfloat16* __restrict__ Ahi, const __nv_bfloat16* __restrict__ Alo,
    const __nv_bfloat16* __restrict__ Bhi, const __nv_bfloat16* __restrict__ Blo,
    float* __restrict__ C, int M, int N, int K)
{
    extern __shared__ __align__(16) char smem[];
    const uint32_t sb = smem_u32(smem);
    const int tid = threadIdx.x;
    const int wid = tid >> 5;
    const int lane = tid & 31;
    const int m0 = blockIdx.y * BM;
    const int n0 = blockIdx.x * BN;
    const int wm = (wid & 3) * 32;
    const int wn = (wid >> 2) * 64;

    const __nv_bfloat16* srcs[4] = {Ahi, Alo, Bhi, Blo};

    float acc[2][8][4];
    #pragma unroll
    for (int mi = 0; mi < 2; mi++)
        #pragma unroll
        for (int ni = 0; ni < 8; ni++)
            #pragma unroll
            for (int e = 0; e < 4; e++) acc[mi][ni][e] = 0.f;

    auto fill = [&](int stage, int k0) {
        const uint32_t sbase = sb + stage * STAGE_B;
        #pragma unroll
        for (int it = 0; it < 8; it++) {
            int i = it * 256 + tid;
            int op = i >> 9;
            int r  = (i >> 2) & 127;
            int c  = i & 3;
            int rowg = (op < 2) ? (m0 + r) : (n0 + r);
            const __nv_bfloat16* src = srcs[op] + (size_t)rowg * K + k0 + c * 8;
            uint32_t dst = sbase + op * TILE_B + r * ROWB + c * 16;
            cpa16(dst, src);
        }
        CP_COMMIT();
    };

    const int nch = K / BKC;
    fill(0, 0);
    fill(1, BKC);

    const int r4 = lane >> 2;
    const int k4 = lane & 3;

    for (int c = 0; c < nch; c++) {
        const int s = c & 1;
        if (c + 1 < nch) CP_WAIT1(); else CP_WAIT0();
        __syncthreads();

        const uint32_t sbase = sb + s * STAGE_B;
        const uint32_t aHi = sbase;
        const uint32_t aLo = sbase + TILE_B;
        const uint32_t bHi = sbase + 2 * TILE_B;
        const uint32_t bLo = sbase + 3 * TILE_B;

        #pragma unroll
        for (int ks = 0; ks < 2; ks++) {
            const uint32_t kb = ks * 32 + k4 * 4;

            uint32_t ah[2][4], al[2][4], bh[8][2], bl[8][2];
            #pragma unroll
            for (int mi = 0; mi < 2; mi++) {
                uint32_t ro = (wm + mi * 16 + r4) * ROWB + kb;
                asm volatile("ld.shared.b32 %0, [%1];" : "=r"(ah[mi][0]) : "r"(aHi + ro));
                asm volatile("ld.shared.b32 %0, [%1];" : "=r"(ah[mi][1]) : "r"(aHi + ro + 8 * ROWB));
                asm volatile("ld.shared.b32 %0, [%1];" : "=r"(ah[mi][2]) : "r"(aHi + ro + 16));
                asm volatile("ld.shared.b32 %0, [%1];" : "=r"(ah[mi][3]) : "r"(aHi + ro + 8 * ROWB + 16));
                asm volatile("ld.shared.b32 %0, [%1];" : "=r"(al[mi][0]) : "r"(aLo + ro));
                asm volatile("ld.shared.b32 %0, [%1];" : "=r"(al[mi][1]) : "r"(aLo + ro + 8 * ROWB));
                asm volatile("ld.shared.b32 %0, [%1];" : "=r"(al[mi][2]) : "r"(aLo + ro + 16));
                asm volatile("ld.shared.b32 %0, [%1];" : "=r"(al[mi][3]) : "r"(aLo + ro + 8 * ROWB + 16));
            }
            #pragma unroll
            for (int ni = 0; ni < 8; ni++) {
                uint32_t ro = (wn + ni * 8 + r4) * ROWB + kb;
                asm volatile("ld.shared.b32 %0, [%1];" : "=r"(bh[ni][0]) : "r"(bHi + ro));
                asm volatile("ld.shared.b32 %0, [%1];" : "=r"(bh[ni][1]) : "r"(bHi + ro + 16));
                asm volatile("ld.shared.b32 %0, [%1];" : "=r"(bl[ni][0]) : "r"(bLo + ro));
                asm volatile("ld.shared.b32 %0, [%1];" : "=r"(bl[ni][1]) : "r"(bLo + ro + 16));
            }

            #pragma unroll
            for (int mi = 0; mi < 2; mi++)
                #pragma unroll
                for (int ni = 0; ni < 8; ni++) {
                    mma_bf16(acc[mi][ni], ah[mi], bh[ni]);
                    mma_bf16(acc[mi][ni], ah[mi], bl[ni]);
                    mma_bf16(acc[mi][ni], al[mi], bh[ni]);
                }
        }

        __syncthreads();
        if (c + 2 < nch) fill(s, (c + 2) * BKC);
    }

    #pragma unroll
    for (int mi = 0; mi < 2; mi++) {
        int r0 = m0 + wm + mi * 16 + r4;
        #pragma unroll
        for (int ni = 0; ni < 8; ni++) {
            int cc = n0 + wn + ni * 8 + k4 * 2;
            float2 v0 = {acc[mi][ni][0], acc[mi][ni][1]};
            float2 v1 = {acc[mi][ni][2], acc[mi][ni][3]};
            *(float2*)(C + (size_t)r0 * N + cc) = v0;
            *(float2*)(C + (size_t)(r0 + 8) * N + cc) = v1;
        }
    }
}

// ---------------------------------------------------------------------------
// RoPE (in place, fp32 qkv).  positions = arange(S) per batch.
// ---------------------------------------------------------------------------
__global__ __launch_bounds__(256) void rope_kernel(float* __restrict__ qkv) {
    const int idx = blockIdx.x * blockDim.x + threadIdx.x;
    if (idx >= NTOK * HH * 64) return;
    const int d = idx & 63;
    const int h = (idx >> 6) & 15;
    const int t = idx >> 10;

    const float pos = (float)(t % SS);
    const float inv_freq = powf(10000.0f, -(float)d * (1.0f / 64.0f));
    const float ang = pos * inv_freq;
    const float c = cosf(ang), s = sinf(ang);

    float* q = qkv + (size_t)t * QKV_N + h * DHH;
    float x1 = q[d], x2 = q[d + 64];
    q[d]      = x1 * c - x2 * s;
    q[d + 64] = x2 * c + x1 * s;

    float* k = q + DD;
    x1 = k[d]; x2 = k[d + 64];
    k[d]      = x1 * c - x2 * s;
    k[d + 64] = x2 * c + x1 * s;
}

// ---------------------------------------------------------------------------
// Flash attention v2: mma.sync split-bf16 QK^T and PV, register softmax.
// 128 threads (4 warps), each warp owns 16 q-rows of a 64-row Q tile.
// ---------------------------------------------------------------------------
#define QROW 272     // 128 bf16 = 256B data, +16 pad (conflict-free)
#define VROW 144     // 64 bf16 = 128B data, +16 pad
#define F2_QH 0
#define F2_QL (F2_QH + 64 * QROW)
#define F2_KH (F2_QL + 64 * QROW)
#define F2_KL (F2_KH + 64 * QROW)
#define F2_VH (F2_KL + 64 * QROW)
#define F2_VL (F2_VH + 128 * VROW)
#define FLASH2_SMEM (F2_VL + 128 * VROW)   // 106496 bytes

__global__ __launch_bounds__(128) void flash2_kernel(const float* __restrict__ qkv,
                                                     __nv_bfloat16* __restrict__ attn_hi,
                                                     __nv_bfloat16* __restrict__ attn_lo) {
    extern __shared__ __align__(16) char smem[];

    const int qb = blockIdx.x;
    const int h  = blockIdx.y;
    const int b  = blockIdx.z;
    const int tid = threadIdx.x;
    const int wid = tid >> 5;
    const int lane = tid & 31;
    const int r4 = lane >> 2;      // 0..7
    const int k4 = lane & 3;       // 0..3

    const float* qbase = qkv + (size_t)(b * SS) * QKV_N + h * DHH;
    const float* kbase = qbase + DD;
    const float* vbase = qbase + 2 * DD;

    // ---- load Q tile (64 x 128) -> smem hi/lo ----
    for (int i = tid; i < 64 * 32; i += 128) {
        int row = i >> 5, d4 = (i & 31) * 4;
        float4 v = *(const float4*)(qbase + (size_t)(qb * 64 + row) * QKV_N + d4);
        __nv_bfloat16 h0,l0,h1,l1,h2,l2,h3,l3;
        split2(v.x, h0, l0); split2(v.y, h1, l1);
        split2(v.z, h2, l2); split2(v.w, h3, l3);
        uint32_t off = row * QROW + d4 * 2;
        *(uint32_t*)(smem + F2_QH + off)     = packbf(h0, h1);
        *(uint32_t*)(smem + F2_QH + off + 4) = packbf(h2, h3);
        *(uint32_t*)(smem + F2_QL + off)     = packbf(l0, l1);
        *(uint32_t*)(smem + F2_QL + off + 4) = packbf(l2, l3);
    }

    float oacc[16][4];
    #pragma unroll
    for (int n = 0; n < 16; n++)
        #pragma unroll
        for (int e = 0; e < 4; e++) oacc[n][e] = 0.f;

    float m0 = -1e30f, m1 = -1e30f, l0 = 0.f, l1 = 0.f;
    const float scale = 0.088388347648318447f;   // 1/sqrt(128)
    const int arow = wid * 16 + r4;

    for (int kt = 0; kt <= qb; kt++) {
        __syncthreads();
        // ---- load K tile (64 x 128) hi/lo ----
        for (int i = tid; i < 64 * 32; i += 128) {
            int row = i >> 5, d4 = (i & 31) * 4;
            float4 v = *(const float4*)(kbase + (size_t)(kt * 64 + row) * QKV_N + d4);
            __nv_bfloat16 h0,ll0,h1,ll1,h2,ll2,h3,ll3;
            split2(v.x, h0, ll0); split2(v.y, h1, ll1);
            split2(v.z, h2, ll2); split2(v.w, h3, ll3);
            uint32_t off = row * QROW + d4 * 2;
            *(uint32_t*)(smem + F2_KH + off)     = packbf(h0, h1);
            *(uint32_t*)(smem + F2_KH + off + 4) = packbf(h2, h3);
            *(uint32_t*)(smem + F2_KL + off)     = packbf(ll0, ll1);
            *(uint32_t*)(smem + F2_KL + off + 4) = packbf(ll2, ll3);
        }
        // ---- load V tile transposed: VT[dh=tid][key] hi/lo ----
        {
            const float* vcol = vbase + tid;
            #pragma unroll 4
            for (int kk = 0; kk < 64; kk += 2) {
                float v0 = vcol[(size_t)(kt * 64 + kk) * QKV_N];
                float v1 = vcol[(size_t)(kt * 64 + kk + 1) * QKV_N];
                __nv_bfloat16 h0,ll0,h1,ll1;
                split2(v0, h0, ll0); split2(v1, h1, ll1);
                *(uint32_t*)(smem + F2_VH + tid * VROW + kk * 2) = packbf(h0, h1);
                *(uint32_t*)(smem + F2_VL + tid * VROW + kk * 2) = packbf(ll0, ll1);
            }
        }
        __syncthreads();

        // ---- S = Q K^T (split 3-term) ----
        float sacc[8][4];
        #pragma unroll
        for (int n = 0; n < 8; n++)
            #pragma unroll
            for (int e = 0; e < 4; e++) sacc[n][e] = 0.f;

        #pragma unroll
        for (int kb = 0; kb < 8; kb++) {
            const uint32_t koff = kb * 32 + k4 * 4;
            uint32_t ah[4], al[4];
            ah[0] = *(const uint32_t*)(smem + F2_QH + arow * QROW + koff);
            ah[1] = *(const uint32_t*)(smem + F2_QH + (arow + 8) * QROW + koff);
            ah[2] = *(const uint32_t*)(smem + F2_QH + arow * QROW + koff + 16);
            ah[3] = *(const uint32_t*)(smem + F2_QH + (arow + 8) * QROW + koff + 16);
            al[0] = *(const uint32_t*)(smem + F2_QL + arow * QROW + koff);
            al[1] = *(const uint32_t*)(smem + F2_QL + (arow + 8) * QROW + koff);
            al[2] = *(const uint32_t*)(smem + F2_QL + arow * QROW + koff + 16);
            al[3] = *(const uint32_t*)(smem + F2_QL + (arow + 8) * QROW + koff + 16);
            #pragma unroll
            for (int ng = 0; ng < 8; ng++) {
                const uint32_t bro = (ng * 8 + r4) * QROW + koff;
                uint32_t bh[2], bl[2];
                bh[0] = *(const uint32_t*)(smem + F2_KH + bro);
                bh[1] = *(const uint32_t*)(smem + F2_KH + bro + 16);
                bl[0] = *(const uint32_t*)(smem + F2_KL + bro);
                bl[1] = *(const uint32_t*)(smem + F2_KL + bro + 16);
                mma_bf16(sacc[ng], ah, bh);
                mma_bf16(sacc[ng], ah, bl);
                mma_bf16(sacc[ng], al, bh);
            }
        }

        // ---- scale + causal mask ----
        const int row0 = qb * 64 + wid * 16 + r4;
        if (kt == qb) {
            #pragma unroll
            for (int ng = 0; ng < 8; ng++) {
                int colb = kt * 64 + ng * 8 + k4 * 2;
                sacc[ng][0] = (colb     > row0)     ? -1e30f : sacc[ng][0] * scale;
                sacc[ng][1] = (colb + 1 > row0)     ? -1e30f : sacc[ng][1] * scale;
                sacc[ng][2] = (colb     > row0 + 8) ? -1e30f : sacc[ng][2] * scale;
                sacc[ng][3] = (colb + 1 > row0 + 8) ? -1e30f : sacc[ng][3] * scale;
            }
        } else {
            #pragma unroll
            for (int ng = 0; ng < 8; ng++)
                #pragma unroll
                for (int e = 0; e < 4; e++) sacc[ng][e] *= scale;
        }

        // ---- online softmax (rows r4 and r4+8 of this warp's 16) ----
        float mx0 = -1e30f, mx1 = -1e30f;
        #pragma unroll
        for (int ng = 0; ng < 8; ng++) {
            mx0 = fmaxf(mx0, fmaxf(sacc[ng][0], sacc[ng][1]));
            mx1 = fmaxf(mx1, fmaxf(sacc[ng][2], sacc[ng][3]));
        }
        mx0 = fmaxf(mx0, __shfl_xor_sync(0xffffffffu, mx0, 1));
        mx0 = fmaxf(mx0, __shfl_xor_sync(0xffffffffu, mx0, 2));
        mx1 = fmaxf(mx1, __shfl_xor_sync(0xffffffffu, mx1, 1));
        mx1 = fmaxf(mx1, __shfl_xor_sync(0xffffffffu, mx1, 2));

        float mn0 = fmaxf(m0, mx0), mn1 = fmaxf(m1, mx1);
        float c0 = __expf(m0 - mn0), c1 = __expf(m1 - mn1);
        m0 = mn0; m1 = mn1;

        float sum0 = 0.f, sum1 = 0.f;
        uint32_t ph2[8][2], pl2[8][2];
        #pragma unroll
        for (int ng = 0; ng < 8; ng++) {
            float p0 = __expf(sacc[ng][0] - m0);
            float p1 = __expf(sacc[ng][1] - m0);
            float p2 = __expf(sacc[ng][2] - m1);
            float p3 = __expf(sacc[ng][3] - m1);
            sum0 += p0 + p1; sum1 += p2 + p3;
            __nv_bfloat16 a,bq,cc,dd2, la,lb,lc,ld;
            split2(p0, a, la); split2(p1, bq, lb);
            split2(p2, cc, lc); split2(p3, dd2, ld);
            ph2[ng][0] = packbf(a, bq);  ph2[ng][1] = packbf(cc, dd2);
            pl2[ng][0] = packbf(la, lb); pl2[ng][1] = packbf(lc, ld);
        }
        sum0 += __shfl_xor_sync(0xffffffffu, sum0, 1);
        sum0 += __shfl_xor_sync(0xffffffffu, sum0, 2);
        sum1 += __shfl_xor_sync(0xffffffffu, sum1, 1);
        sum1 += __shfl_xor_sync(0xffffffffu, sum1, 2);
        l0 = l0 * c0 + sum0;
        l1 = l1 * c1 + sum1;

        #pragma unroll
        for (int n = 0; n < 16; n++) {
            oacc[n][0] *= c0; oacc[n][1] *= c0;
            oacc[n][2] *= c1; oacc[n][3] *= c1;
        }

        // ---- O += P V (split 3-term), V^T in smem [dh][key] ----
        #pragma unroll
        for (int kb = 0; kb < 4; kb++) {
            uint32_t pa[4] = {ph2[2*kb][0], ph2[2*kb][1], ph2[2*kb+1][0], ph2[2*kb+1][1]};
            uint32_t pb[4] = {pl2[2*kb][0], pl2[2*kb][1], pl2[2*kb+1][0], pl2[2*kb+1][1]};
            const uint32_t koff = kb * 32 + k4 * 4;
            #pragma unroll
            for (int ng = 0; ng < 16; ng++) {
                const uint32_t vro = (ng * 8 + r4) * VROW + koff;
                uint32_t vh[2], vl[2];
                vh[0] = *(const uint32_t*)(smem + F2_VH + vro);
                vh[1] = *(const uint32_t*)(smem + F2_VH + vro + 16);
                vl[0] = *(const uint32_t*)(smem + F2_VL + vro);
                vl[1] = *(const uint32_t*)(smem + F2_VL + vro + 16);
                mma_bf16(oacc[ng], pa, vh);
                mma_bf16(oacc[ng], pa, vl);
                mma_bf16(oacc[ng], pb, vh);
            }
        }
    }

    // ---- epilogue: normalize, split, store ----
    const float inv0 = 1.0f / l0, inv1 = 1.0f / l1;
    const int grow0 = b * SS + qb * 64 + wid * 16 + r4;
    #pragma unroll
    for (int ng = 0; ng < 16; ng++) {
        size_t o0 = (size_t)grow0 * DD + h * DHH + ng * 8 + k4 * 2;
        size_t o1 = o0 + (size_t)8 * DD;
        float v0 = oacc[ng][0] * inv0, v1 = oacc[ng][1] * inv0;
        float v2 = oacc[ng][2] * inv1, v3 = oacc[ng][3] * inv1;
        __nv_bfloat16 hh, ll;
        __nv_bfloat16 h0,l0b,h1,l1b,h2,l2b,h3,l3b;
        split2(v0, h0, l0b); split2(v1, h1, l1b);
        split2(v2, h2, l2b); split2(v3, h3, l3b);
        *(uint32_t*)(attn_hi + o0) = packbf(h0, h1);
        *(uint32_t*)(attn_lo + o0) = packbf(l0b, l1b);
        *(uint32_t*)(attn_hi + o1) = packbf(h2, h3);
        *(uint32_t*)(attn_lo + o1) = packbf(l2b, l3b);
        (void)hh; (void)ll;
    }
}

// ---------------------------------------------------------------------------
// kernel_launch: inputs = [positions, hidden_states, w_qkv, w_out]
// ---------------------------------------------------------------------------
extern "C" void kernel_launch(void* const* d_in, const int* in_sizes, int n_in,
                              void* d_out, int out_size) {
    const float* hidden = (const float*)d_in[1];
    const float* w_qkv  = (const float*)d_in[2];
    const float* w_out  = (const float*)d_in[3];
    float* out = (float*)d_out;

    __nv_bfloat16 *xh, *xl, *wqh, *wql, *woh, *wol, *ah, *al;
    float* qkv;
    cudaGetSymbolAddress((void**)&xh,  g_xln_hi);
    cudaGetSymbolAddress((void**)&xl,  g_xln_lo);
    cudaGetSymbolAddress((void**)&qkv, g_qkv);
    cudaGetSymbolAddress((void**)&wqh, g_wqkvT_hi);
    cudaGetSymbolAddress((void**)&wql, g_wqkvT_lo);
    cudaGetSymbolAddress((void**)&woh, g_woutT_hi);
    cudaGetSymbolAddress((void**)&wol, g_woutT_lo);
    cudaGetSymbolAddress((void**)&ah,  g_attn_hi);
    cudaGetSymbolAddress((void**)&al,  g_attn_lo);

    // 1) LayerNorm -> split bf16
    ln_kernel<<<NTOK, 256>>>(hidden, xh, xl);

    // 2) Weight transpose+split
    dim3 tb(32, 8);
    transpose_split<<<dim3(QKV_N / 32, DD / 32), tb>>>(w_qkv, wqh, wql, DD, QKV_N);
    transpose_split<<<dim3(DD / 32, DD / 32), tb>>>(w_out, woh, wol, DD, DD);

    // 3) QKV projection (tensor cores via mma.sync)
    cudaFuncSetAttribute(gemm_mma, cudaFuncAttributeMaxDynamicSharedMemorySize, GEMM_SMEM);
    gemm_mma<<<dim3(QKV_N / BN, NTOK / BM), 256, GEMM_SMEM>>>(
        xh, xl, wqh, wql, qkv, NTOK, QKV_N, DD);

    // 4) RoPE
    rope_kernel<<<(NTOK * HH * 64 + 255) / 256, 256>>>(qkv);

    // 5) Causal flash attention v2 (tensor cores) -> split bf16
    cudaFuncSetAttribute(flash2_kernel, cudaFuncAttributeMaxDynamicSharedMemorySize,
                         FLASH2_SMEM);
    flash2_kernel<<<dim3(SS / 64, HH, BB), 128, FLASH2_SMEM>>>(qkv, ah, al);

    // 6) Output projection (tensor cores via mma.sync)
    gemm_mma<<<dim3(DD / BN, NTOK / BM), 256, GEMM_SMEM>>>(
        ah, al, woh, wol, out, NTOK, DD, DD);
}

// round 5
// speedup vs baseline: 2.5583x; 1.0718x over previous
#include <cuda_runtime.h>
#include <cuda_bf16.h>
#include <math.h>
#include <cstdint>

// ---------------------------------------------------------------------------
// Problem constants: B=2, S=2048, D=2048, H=16, DH=128
// ---------------------------------------------------------------------------
#define BB 2
#define SS 2048
#define DD 2048
#define HH 16
#define DHH 128
#define NTOK (BB * SS)          // 4096
#define QKV_N (3 * DD)          // 6144
#define LN_EPS 1e-5f

// ---------------------------------------------------------------------------
// Scratch (device globals; allocation forbidden)
// ---------------------------------------------------------------------------
__device__ __nv_bfloat16 g_xln_hi[(size_t)NTOK * DD];
__device__ __nv_bfloat16 g_xln_lo[(size_t)NTOK * DD];
__device__ float         g_qkv[(size_t)NTOK * QKV_N];     // 100.7 MB
__device__ __nv_bfloat16 g_wqkvT_hi[(size_t)QKV_N * DD];
__device__ __nv_bfloat16 g_wqkvT_lo[(size_t)QKV_N * DD];
__device__ __nv_bfloat16 g_woutT_hi[(size_t)DD * DD];
__device__ __nv_bfloat16 g_woutT_lo[(size_t)DD * DD];
__device__ __nv_bfloat16 g_attn_hi[(size_t)NTOK * DD];
__device__ __nv_bfloat16 g_attn_lo[(size_t)NTOK * DD];

// ---------------------------------------------------------------------------
// helpers
// ---------------------------------------------------------------------------
__device__ __forceinline__ uint32_t smem_u32(const void* p) {
    uint32_t a;
    asm("{ .reg .u64 t; cvta.to.shared.u64 t, %1; cvt.u32.u64 %0, t; }"
        : "=r"(a) : "l"(p));
    return a;
}

__device__ __forceinline__ void cpa16(uint32_t dst, const void* src) {
    asm volatile("cp.async.cg.shared.global [%0], [%1], 16;" :: "r"(dst), "l"(src) : "memory");
}
#define CP_COMMIT() asm volatile("cp.async.commit_group;" ::: "memory")
#define CP_WAIT1()  asm volatile("cp.async.wait_group 1;" ::: "memory")
#define CP_WAIT0()  asm volatile("cp.async.wait_group 0;" ::: "memory")

__device__ __forceinline__ void mma_bf16(float* c, const uint32_t* a, const uint32_t* b) {
    asm volatile(
        "mma.sync.aligned.m16n8k16.row.col.f32.bf16.bf16.f32 "
        "{%0,%1,%2,%3}, {%4,%5,%6,%7}, {%8,%9}, {%0,%1,%2,%3};"
        : "+f"(c[0]), "+f"(c[1]), "+f"(c[2]), "+f"(c[3])
        : "r"(a[0]), "r"(a[1]), "r"(a[2]), "r"(a[3]), "r"(b[0]), "r"(b[1]));
}

__device__ __forceinline__ void ldm_x4(uint32_t* r, uint32_t addr) {
    asm volatile("ldmatrix.sync.aligned.m8n8.x4.shared.b16 {%0,%1,%2,%3}, [%4];"
        : "=r"(r[0]), "=r"(r[1]), "=r"(r[2]), "=r"(r[3]) : "r"(addr));
}

__device__ __forceinline__ void split2(float v, __nv_bfloat16& h, __nv_bfloat16& l) {
    h = __float2bfloat16(v);
    l = __float2bfloat16(v - __bfloat162float(h));
}

__device__ __forceinline__ uint32_t packbf(__nv_bfloat16 a, __nv_bfloat16 b) {
    __nv_bfloat162 t(a, b);   // a = low element
    return *(uint32_t*)&t;
}

// ---------------------------------------------------------------------------
// LayerNorm -> bf16 hi/lo split outputs
// ---------------------------------------------------------------------------
__global__ __launch_bounds__(256) void ln_kernel(const float* __restrict__ x,
                                                 __nv_bfloat16* __restrict__ yh,
                                                 __nv_bfloat16* __restrict__ yl) {
    __shared__ float red_s[8], red_ss[8];
    __shared__ float sh_mu, sh_rstd;
    const int row = blockIdx.x;
    const int tid = threadIdx.x;
    const float* xr = x + (size_t)row * DD;

    float4 a = *(const float4*)(xr + tid * 4);
    float4 b = *(const float4*)(xr + 1024 + tid * 4);
    float s  = a.x + a.y + a.z + a.w + b.x + b.y + b.z + b.w;
    float ss = a.x*a.x + a.y*a.y + a.z*a.z + a.w*a.w
             + b.x*b.x + b.y*b.y + b.z*b.z + b.w*b.w;
    #pragma unroll
    for (int o = 16; o > 0; o >>= 1) {
        s  += __shfl_xor_sync(0xffffffffu, s, o);
        ss += __shfl_xor_sync(0xffffffffu, ss, o);
    }
    const int wid = tid >> 5, lane = tid & 31;
    if (lane == 0) { red_s[wid] = s; red_ss[wid] = ss; }
    __syncthreads();
    if (tid == 0) {
        float S = 0.f, SSq = 0.f;
        #pragma unroll
        for (int w = 0; w < 8; w++) { S += red_s[w]; SSq += red_ss[w]; }
        float mu = S * (1.0f / DD);
        float var = SSq * (1.0f / DD) - mu * mu;
        sh_mu = mu;
        sh_rstd = rsqrtf(var + LN_EPS);
    }
    __syncthreads();
    const float mu = sh_mu, rstd = sh_rstd;
    float va[8] = {a.x, a.y, a.z, a.w, b.x, b.y, b.z, b.w};
    #pragma unroll
    for (int e = 0; e < 8; e++) {
        float v = (va[e] - mu) * rstd;
        __nv_bfloat16 h, l;
        split2(v, h, l);
        size_t col = (e < 4) ? (tid * 4 + e) : (1024 + tid * 4 + e - 4);
        yh[(size_t)row * DD + col] = h;
        yl[(size_t)row * DD + col] = l;
    }
}

// ---------------------------------------------------------------------------
// Transpose + split: W[K][N] fp32 -> hi/lo bf16 [N][K]
// ---------------------------------------------------------------------------
__global__ __launch_bounds__(256) void transpose_split(const float* __restrict__ W,
                                                       __nv_bfloat16* __restrict__ hi,
                                                       __nv_bfloat16* __restrict__ lo,
                                                       int K, int N) {
    __shared__ float t[32][33];
    int n = blockIdx.x * 32 + threadIdx.x;
    int k = blockIdx.y * 32 + threadIdx.y;
    #pragma unroll
    for (int i = 0; i < 4; i++)
        t[threadIdx.y + 8 * i][threadIdx.x] = W[(size_t)(k + 8 * i) * N + n];
    __syncthreads();
    int ko = blockIdx.y * 32 + threadIdx.x;
    int no = blockIdx.x * 32 + threadIdx.y;
    #pragma unroll
    for (int i = 0; i < 4; i++) {
        float v = t[threadIdx.x][threadIdx.y + 8 * i];
        __nv_bfloat16 h, l;
        split2(v, h, l);
        size_t o = (size_t)(no + 8 * i) * K + ko;
        hi[o] = h;
        lo[o] = l;
    }
}

// ---------------------------------------------------------------------------
// mma.sync split-bf16 GEMM v2: C[M,N] fp32 = (Ahi+Alo)[M,K] @ (Bhi+Blo)[N,K]^T
// CTA tile 128x256, BK=32, 8 warps (2x4), warp tile 64x64.
// ldmatrix fragment loads; term-major MMA ordering.
// ---------------------------------------------------------------------------
#define BM 128
#define BN 256
#define BKC 32
#define ROWB 80                       // padded row bytes (32 bf16 = 64B data)
#define A_TILE (128 * ROWB)           // 10240
#define B_TILE (256 * ROWB)           // 20480
#define STAGE_B (2 * A_TILE + 2 * B_TILE)   // 61440
#define GEMM_SMEM (2 * STAGE_B)             // 122880

__global__ __launch_bounds__(256, 1) void gemm_mma(
    const __nv_bfloat16* __restrict__ Ahi, const __nv_bfloat16* __restrict__ Alo,
    const __nv_bfloat16* __restrict__ Bhi, const __nv_bfloat16* __restrict__ Blo,
    float* __restrict__ C, int M, int N, int K)
{
    extern __shared__ __align__(16) char smem[];
    const uint32_t sb = smem_u32(smem);
    const int tid = threadIdx.x;
    const int wid = tid >> 5;
    const int lane = tid & 31;
    const int m0 = blockIdx.y * BM;
    const int n0 = blockIdx.x * BN;
    const int wm = (wid & 1) * 64;        // warp m offset (0 or 64)
    const int wn = (wid >> 1) * 64;       // warp n offset (0,64,128,192)

    float acc[4][8][4];
    #pragma unroll
    for (int mi = 0; mi < 4; mi++)
        #pragma unroll
        for (int ni = 0; ni < 8; ni++)
            #pragma unroll
            for (int e = 0; e < 4; e++) acc[mi][ni][e] = 0.f;

    auto fill = [&](int stage, int k0) {
        const uint32_t sbase = sb + stage * STAGE_B;
        #pragma unroll
        for (int it = 0; it < 12; it++) {
            int i = it * 256 + tid;               // 3072 x 16B chunks
            const __nv_bfloat16* src;
            uint32_t dst;
            if (i < 1024) {                        // A hi/lo: 2 x 128 rows x 4
                int op = i >> 9, r = (i >> 2) & 127, c = i & 3;
                src = (op ? Alo : Ahi) + (size_t)(m0 + r) * K + k0 + c * 8;
                dst = sbase + op * A_TILE + r * ROWB + c * 16;
            } else {                               // B hi/lo: 2 x 256 rows x 4
                int j = i - 1024;
                int op = j >> 10, r = (j >> 2) & 255, c = j & 3;
                src = (op ? Blo : Bhi) + (size_t)(n0 + r) * K + k0 + c * 8;
                dst = sbase + 2 * A_TILE + op * B_TILE + r * ROWB + c * 16;
            }
            cpa16(dst, src);
        }
        CP_COMMIT();
    };

    const int nch = K / BKC;
    fill(0, 0);
    fill(1, BKC);

    // ldmatrix lane-address components
    const int lg = lane >> 3;     // 0..3 (8-lane group)
    const int lr = lane & 7;      // row within group

    for (int c = 0; c < nch; c++) {
        const int s = c & 1;
        if (c + 1 < nch) CP_WAIT1(); else CP_WAIT0();
        __syncthreads();

        const uint32_t sbase = sb + s * STAGE_B;
        const uint32_t aHi = sbase;
        const uint32_t aLo = sbase + A_TILE;
        const uint32_t bHi = sbase + 2 * A_TILE;
        const uint32_t bLo = sbase + 2 * A_TILE + B_TILE;

        #pragma unroll
        for (int ks = 0; ks < 2; ks++) {
            const uint32_t koff = ks * 32;

            // A fragments: lanes map (g0: m+lr,k0) (g1: m+8+lr,k0) (g2: m+lr,k16) (g3: m+8+lr,k16)
            const uint32_t aoff = (lg & 1) * 8 * ROWB + (lg >> 1) * 16 + lr * ROWB + koff;
            uint32_t ah[4][4], al[4][4];
            #pragma unroll
            for (int mi = 0; mi < 4; mi++) {
                uint32_t ro = (wm + mi * 16) * ROWB + aoff;
                ldm_x4(ah[mi], aHi + ro);
                ldm_x4(al[mi], aLo + ro);
            }
            // B fragments: x4 covers two n-groups: (g0: n+lr,k0) (g1: n+lr,k16) (g2: n+8+lr,k0) (g3: n+8+lr,k16)
            const uint32_t boff = (lg >> 1) * 8 * ROWB + (lg & 1) * 16 + lr * ROWB + koff;
            uint32_t bh[8][2], bl[8][2];
            #pragma unroll
            for (int np = 0; np < 4; np++) {
                uint32_t ro = (wn + np * 16) * ROWB + boff;
                uint32_t t4[4];
                ldm_x4(t4, bHi + ro);
                bh[2 * np][0] = t4[0]; bh[2 * np][1] = t4[1];
                bh[2 * np + 1][0] = t4[2]; bh[2 * np + 1][1] = t4[3];
                ldm_x4(t4, bLo + ro);
                bl[2 * np][0] = t4[0]; bl[2 * np][1] = t4[1];
                bl[2 * np + 1][0] = t4[2]; bl[2 * np + 1][1] = t4[3];
            }

            // term-major: break same-accumulator chains
            #pragma unroll
            for (int mi = 0; mi < 4; mi++)
                #pragma unroll
                for (int ni = 0; ni < 8; ni++)
                    mma_bf16(acc[mi][ni], ah[mi], bh[ni]);
            #pragma unroll
            for (int mi = 0; mi < 4; mi++)
                #pragma unroll
                for (int ni = 0; ni < 8; ni++)
                    mma_bf16(acc[mi][ni], ah[mi], bl[ni]);
            #pragma unroll
            for (int mi = 0; mi < 4; mi++)
                #pragma unroll
                for (int ni = 0; ni < 8; ni++)
                    mma_bf16(acc[mi][ni], al[mi], bh[ni]);
        }

        __syncthreads();
        if (c + 2 < nch) fill(s, (c + 2) * BKC);
    }

    const int r4 = lane >> 2;
    const int k4 = lane & 3;
    #pragma unroll
    for (int mi = 0; mi < 4; mi++) {
        int r0 = m0 + wm + mi * 16 + r4;
        #pragma unroll
        for (int ni = 0; ni < 8; ni++) {
            int cc = n0 + wn + ni * 8 + k4 * 2;
            float2 v0 = {acc[mi][ni][0], acc[mi][ni][1]};
            float2 v1 = {acc[mi][ni][2], acc[mi][ni][3]};
            *(float2*)(C + (size_t)r0 * N + cc) = v0;
            *(float2*)(C + (size_t)(r0 + 8) * N + cc) = v1;
        }
    }
}

// ---------------------------------------------------------------------------
// RoPE (in place, fp32 qkv).  positions = arange(S) per batch.
// ---------------------------------------------------------------------------
__global__ __launch_bounds__(256) void rope_kernel(float* __restrict__ qkv) {
    const int idx = blockIdx.x * blockDim.x + threadIdx.x;
    if (idx >= NTOK * HH * 64) return;
    const int d = idx & 63;
    const int h = (idx >> 6) & 15;
    const int t = idx >> 10;

    const float pos = (float)(t % SS);
    const float inv_freq = powf(10000.0f, -(float)d * (1.0f / 64.0f));
    const float ang = pos * inv_freq;
    const float c = cosf(ang), s = sinf(ang);

    float* q = qkv + (size_t)t * QKV_N + h * DHH;
    float x1 = q[d], x2 = q[d + 64];
    q[d]      = x1 * c - x2 * s;
    q[d + 64] = x2 * c + x1 * s;

    float* k = q + DD;
    x1 = k[d]; x2 = k[d + 64];
    k[d]      = x1 * c - x2 * s;
    k[d + 64] = x2 * c + x1 * s;
}

// ---------------------------------------------------------------------------
// Flash attention v2 (unchanged from round 4 — proven)
// ---------------------------------------------------------------------------
#define QROW 272
#define VROW 144
#define F2_QH 0
#define F2_QL (F2_QH + 64 * QROW)
#define F2_KH (F2_QL + 64 * QROW)
#define F2_KL (F2_KH + 64 * QROW)
#define F2_VH (F2_KL + 64 * QROW)
#define F2_VL (F2_VH + 128 * VROW)
#define FLASH2_SMEM (F2_VL + 128 * VROW)   // 106496 bytes

__global__ __launch_bounds__(128) void flash2_kernel(const float* __restrict__ qkv,
                                                     __nv_bfloat16* __restrict__ attn_hi,
                                                     __nv_bfloat16* __restrict__ attn_lo) {
    extern __shared__ __align__(16) char smem[];

    const int qb = blockIdx.x;
    const int h  = blockIdx.y;
    const int b  = blockIdx.z;
    const int tid = threadIdx.x;
    const int wid = tid >> 5;
    const int lane = tid & 31;
    const int r4 = lane >> 2;
    const int k4 = lane & 3;

    const float* qbase = qkv + (size_t)(b * SS) * QKV_N + h * DHH;
    const float* kbase = qbase + DD;
    const float* vbase = qbase + 2 * DD;

    for (int i = tid; i < 64 * 32; i += 128) {
        int row = i >> 5, d4 = (i & 31) * 4;
        float4 v = *(const float4*)(qbase + (size_t)(qb * 64 + row) * QKV_N + d4);
        __nv_bfloat16 h0,l0,h1,l1,h2,l2,h3,l3;
        split2(v.x, h0, l0); split2(v.y, h1, l1);
        split2(v.z, h2, l2); split2(v.w, h3, l3);
        uint32_t off = row * QROW + d4 * 2;
        *(uint32_t*)(smem + F2_QH + off)     = packbf(h0, h1);
        *(uint32_t*)(smem + F2_QH + off + 4) = packbf(h2, h3);
        *(uint32_t*)(smem + F2_QL + off)     = packbf(l0, l1);
        *(uint32_t*)(smem + F2_QL + off + 4) = packbf(l2, l3);
    }

    float oacc[16][4];
    #pragma unroll
    for (int n = 0; n < 16; n++)
        #pragma unroll
        for (int e = 0; e < 4; e++) oacc[n][e] = 0.f;

    float m0 = -1e30f, m1 = -1e30f, l0 = 0.f, l1 = 0.f;
    const float scale = 0.088388347648318447f;
    const int arow = wid * 16 + r4;

    for (int kt = 0; kt <= qb; kt++) {
        __syncthreads();
        for (int i = tid; i < 64 * 32; i += 128) {
            int row = i >> 5, d4 = (i & 31) * 4;
            float4 v = *(const float4*)(kbase + (size_t)(kt * 64 + row) * QKV_N + d4);
            __nv_bfloat16 h0,ll0,h1,ll1,h2,ll2,h3,ll3;
            split2(v.x, h0, ll0); split2(v.y, h1, ll1);
            split2(v.z, h2, ll2); split2(v.w, h3, ll3);
            uint32_t off = row * QROW + d4 * 2;
            *(uint32_t*)(smem + F2_KH + off)     = packbf(h0, h1);
            *(uint32_t*)(smem + F2_KH + off + 4) = packbf(h2, h3);
            *(uint32_t*)(smem + F2_KL + off)     = packbf(ll0, ll1);
            *(uint32_t*)(smem + F2_KL + off + 4) = packbf(ll2, ll3);
        }
        {
            const float* vcol = vbase + tid;
            #pragma unroll 4
            for (int kk = 0; kk < 64; kk += 2) {
                float v0 = vcol[(size_t)(kt * 64 + kk) * QKV_N];
                float v1 = vcol[(size_t)(kt * 64 + kk + 1) * QKV_N];
                __nv_bfloat16 h0,ll0,h1,ll1;
                split2(v0, h0, ll0); split2(v1, h1, ll1);
                *(uint32_t*)(smem + F2_VH + tid * VROW + kk * 2) = packbf(h0, h1);
                *(uint32_t*)(smem + F2_VL + tid * VROW + kk * 2) = packbf(ll0, ll1);
            }
        }
        __syncthreads();

        float sacc[8][4];
        #pragma unroll
        for (int n = 0; n < 8; n++)
            #pragma unroll
            for (int e = 0; e < 4; e++) sacc[n][e] = 0.f;

        #pragma unroll
        for (int kb = 0; kb < 8; kb++) {
            const uint32_t koff = kb * 32 + k4 * 4;
            uint32_t ah[4], al[4];
            ah[0] = *(const uint32_t*)(smem + F2_QH + arow * QROW + koff);
            ah[1] = *(const uint32_t*)(smem + F2_QH + (arow + 8) * QROW + koff);
            ah[2] = *(const uint32_t*)(smem + F2_QH + arow * QROW + koff + 16);
            ah[3] = *(const uint32_t*)(smem + F2_QH + (arow + 8) * QROW + koff + 16);
            al[0] = *(const uint32_t*)(smem + F2_QL + arow * QROW + koff);
            al[1] = *(const uint32_t*)(smem + F2_QL + (arow + 8) * QROW + koff);
            al[2] = *(const uint32_t*)(smem + F2_QL + arow * QROW + koff + 16);
            al[3] = *(const uint32_t*)(smem + F2_QL + (arow + 8) * QROW + koff + 16);
            #pragma unroll
            for (int ng = 0; ng < 8; ng++) {
                const uint32_t bro = (ng * 8 + r4) * QROW + koff;
                uint32_t bh[2], bl[2];
                bh[0] = *(const uint32_t*)(smem + F2_KH + bro);
                bh[1] = *(const uint32_t*)(smem + F2_KH + bro + 16);
                bl[0] = *(const uint32_t*)(smem + F2_KL + bro);
                bl[1] = *(const uint32_t*)(smem + F2_KL + bro + 16);
                mma_bf16(sacc[ng], ah, bh);
                mma_bf16(sacc[ng], ah, bl);
                mma_bf16(sacc[ng], al, bh);
            }
        }

        const int row0 = qb * 64 + wid * 16 + r4;
        if (kt == qb) {
            #pragma unroll
            for (int ng = 0; ng < 8; ng++) {
                int colb = kt * 64 + ng * 8 + k4 * 2;
                sacc[ng][0] = (colb     > row0)     ? -1e30f : sacc[ng][0] * scale;
                sacc[ng][1] = (colb + 1 > row0)     ? -1e30f : sacc[ng][1] * scale;
                sacc[ng][2] = (colb     > row0 + 8) ? -1e30f : sacc[ng][2] * scale;
                sacc[ng][3] = (colb + 1 > row0 + 8) ? -1e30f : sacc[ng][3] * scale;
            }
        } else {
            #pragma unroll
            for (int ng = 0; ng < 8; ng++)
                #pragma unroll
                for (int e = 0; e < 4; e++) sacc[ng][e] *= scale;
        }

        float mx0 = -1e30f, mx1 = -1e30f;
        #pragma unroll
        for (int ng = 0; ng < 8; ng++) {
            mx0 = fmaxf(mx0, fmaxf(sacc[ng][0], sacc[ng][1]));
            mx1 = fmaxf(mx1, fmaxf(sacc[ng][2], sacc[ng][3]));
        }
        mx0 = fmaxf(mx0, __shfl_xor_sync(0xffffffffu, mx0, 1));
        mx0 = fmaxf(mx0, __shfl_xor_sync(0xffffffffu, mx0, 2));
        mx1 = fmaxf(mx1, __shfl_xor_sync(0xffffffffu, mx1, 1));
        mx1 = fmaxf(mx1, __shfl_xor_sync(0xffffffffu, mx1, 2));

        float mn0 = fmaxf(m0, mx0), mn1 = fmaxf(m1, mx1);
        float c0 = __expf(m0 - mn0), c1 = __expf(m1 - mn1);
        m0 = mn0; m1 = mn1;

        float sum0 = 0.f, sum1 = 0.f;
        uint32_t ph2[8][2], pl2[8][2];
        #pragma unroll
        for (int ng = 0; ng < 8; ng++) {
            float p0 = __expf(sacc[ng][0] - m0);
            float p1 = __expf(sacc[ng][1] - m0);
            float p2 = __expf(sacc[ng][2] - m1);
            float p3 = __expf(sacc[ng][3] - m1);
            sum0 += p0 + p1; sum1 += p2 + p3;
            __nv_bfloat16 a,bq,cc,dd2, la,lb,lc,ld;
            split2(p0, a, la); split2(p1, bq, lb);
            split2(p2, cc, lc); split2(p3, dd2, ld);
            ph2[ng][0] = packbf(a, bq);  ph2[ng][1] = packbf(cc, dd2);
            pl2[ng][0] = packbf(la, lb); pl2[ng][1] = packbf(lc, ld);
        }
        sum0 += __shfl_xor_sync(0xffffffffu, sum0, 1);
        sum0 += __shfl_xor_sync(0xffffffffu, sum0, 2);
        sum1 += __shfl_xor_sync(0xffffffffu, sum1, 1);
        sum1 += __shfl_xor_sync(0xffffffffu, sum1, 2);
        l0 = l0 * c0 + sum0;
        l1 = l1 * c1 + sum1;

        #pragma unroll
        for (int n = 0; n < 16; n++) {
            oacc[n][0] *= c0; oacc[n][1] *= c0;
            oacc[n][2] *= c1; oacc[n][3] *= c1;
        }

        #pragma unroll
        for (int kb = 0; kb < 4; kb++) {
            uint32_t pa[4] = {ph2[2*kb][0], ph2[2*kb][1], ph2[2*kb+1][0], ph2[2*kb+1][1]};
            uint32_t pb[4] = {pl2[2*kb][0], pl2[2*kb][1], pl2[2*kb+1][0], pl2[2*kb+1][1]};
            const uint32_t koff = kb * 32 + k4 * 4;
            #pragma unroll
            for (int ng = 0; ng < 16; ng++) {
                const uint32_t vro = (ng * 8 + r4) * VROW + koff;
                uint32_t vh[2], vl[2];
                vh[0] = *(const uint32_t*)(smem + F2_VH + vro);
                vh[1] = *(const uint32_t*)(smem + F2_VH + vro + 16);
                vl[0] = *(const uint32_t*)(smem + F2_VL + vro);
                vl[1] = *(const uint32_t*)(smem + F2_VL + vro + 16);
                mma_bf16(oacc[ng], pa, vh);
                mma_bf16(oacc[ng], pa, vl);
                mma_bf16(oacc[ng], pb, vh);
            }
        }
    }

    const float inv0 = 1.0f / l0, inv1 = 1.0f / l1;
    const int grow0 = b * SS + qb * 64 + wid * 16 + r4;
    #pragma unroll
    for (int ng = 0; ng < 16; ng++) {
        size_t o0 = (size_t)grow0 * DD + h * DHH + ng * 8 + k4 * 2;
        size_t o1 = o0 + (size_t)8 * DD;
        float v0 = oacc[ng][0] * inv0, v1 = oacc[ng][1] * inv0;
        float v2 = oacc[ng][2] * inv1, v3 = oacc[ng][3] * inv1;
        __nv_bfloat16 h0,l0b,h1,l1b,h2,l2b,h3,l3b;
        split2(v0, h0, l0b); split2(v1, h1, l1b);
        split2(v2, h2, l2b); split2(v3, h3, l3b);
        *(uint32_t*)(attn_hi + o0) = packbf(h0, h1);
        *(uint32_t*)(attn_lo + o0) = packbf(l0b, l1b);
        *(uint32_t*)(attn_hi + o1) = packbf(h2, h3);
        *(uint32_t*)(attn_lo + o1) = packbf(l2b, l3b);
    }
}

// ---------------------------------------------------------------------------
// kernel_launch: inputs = [positions, hidden_states, w_qkv, w_out]
// ---------------------------------------------------------------------------
extern "C" void kernel_launch(void* const* d_in, const int* in_sizes, int n_in,
                              void* d_out, int out_size) {
    const float* hidden = (const float*)d_in[1];
    const float* w_qkv  = (const float*)d_in[2];
    const float* w_out  = (const float*)d_in[3];
    float* out = (float*)d_out;

    __nv_bfloat16 *xh, *xl, *wqh, *wql, *woh, *wol, *ah, *al;
    float* qkv;
    cudaGetSymbolAddress((void**)&xh,  g_xln_hi);
    cudaGetSymbolAddress((void**)&xl,  g_xln_lo);
    cudaGetSymbolAddress((void**)&qkv, g_qkv);
    cudaGetSymbolAddress((void**)&wqh, g_wqkvT_hi);
    cudaGetSymbolAddress((void**)&wql, g_wqkvT_lo);
    cudaGetSymbolAddress((void**)&woh, g_woutT_hi);
    cudaGetSymbolAddress((void**)&wol, g_woutT_lo);
    cudaGetSymbolAddress((void**)&ah,  g_attn_hi);
    cudaGetSymbolAddress((void**)&al,  g_attn_lo);

    // 1) LayerNorm -> split bf16
    ln_kernel<<<NTOK, 256>>>(hidden, xh, xl);

    // 2) Weight transpose+split
    dim3 tb(32, 8);
    transpose_split<<<dim3(QKV_N / 32, DD / 32), tb>>>(w_qkv, wqh, wql, DD, QKV_N);
    transpose_split<<<dim3(DD / 32, DD / 32), tb>>>(w_out, woh, wol, DD, DD);

    // 3) QKV projection (tensor cores via mma.sync)
    cudaFuncSetAttribute(gemm_mma, cudaFuncAttributeMaxDynamicSharedMemorySize, GEMM_SMEM);
    gemm_mma<<<dim3(QKV_N / BN, NTOK / BM), 256, GEMM_SMEM>>>(
        xh, xl, wqh, wql, qkv, NTOK, QKV_N, DD);

    // 4) RoPE
    rope_kernel<<<(NTOK * HH * 64 + 255) / 256, 256>>>(qkv);

    // 5) Causal flash attention v2 (tensor cores) -> split bf16
    cudaFuncSetAttribute(flash2_kernel, cudaFuncAttributeMaxDynamicSharedMemorySize,
                         FLASH2_SMEM);
    flash2_kernel<<<dim3(SS / 64, HH, BB), 128, FLASH2_SMEM>>>(qkv, ah, al);

    // 6) Output projection (tensor cores via mma.sync)
    gemm_mma<<<dim3(DD / BN, NTOK / BM), 256, GEMM_SMEM>>>(
        ah, al, woh, wol, out, NTOK, DD, DD);
}

// round 6
// speedup vs baseline: 2.5887x; 1.0119x over previous
#include <cuda_runtime.h>
#include <cuda_bf16.h>
#include <math.h>
#include <cstdint>

// ---------------------------------------------------------------------------
// Problem constants: B=2, S=2048, D=2048, H=16, DH=128
// ---------------------------------------------------------------------------
#define BB 2
#define SS 2048
#define DD 2048
#define HH 16
#define DHH 128
#define NTOK (BB * SS)          // 4096
#define QKV_N (3 * DD)          // 6144
#define LN_EPS 1e-5f

// ---------------------------------------------------------------------------
// Scratch (device globals; allocation forbidden)
// ---------------------------------------------------------------------------
__device__ __nv_bfloat16 g_xln_hi[(size_t)NTOK * DD];
__device__ __nv_bfloat16 g_xln_lo[(size_t)NTOK * DD];
__device__ float         g_qkv[(size_t)NTOK * QKV_N];     // 100.7 MB
__device__ __nv_bfloat16 g_wqkvT_hi[(size_t)QKV_N * DD];
__device__ __nv_bfloat16 g_wqkvT_lo[(size_t)QKV_N * DD];
__device__ __nv_bfloat16 g_woutT_hi[(size_t)DD * DD];
__device__ __nv_bfloat16 g_woutT_lo[(size_t)DD * DD];
__device__ __nv_bfloat16 g_attn_hi[(size_t)NTOK * DD];
__device__ __nv_bfloat16 g_attn_lo[(size_t)NTOK * DD];

// ---------------------------------------------------------------------------
// helpers
// ---------------------------------------------------------------------------
__device__ __forceinline__ uint32_t smem_u32(const void* p) {
    uint32_t a;
    asm("{ .reg .u64 t; cvta.to.shared.u64 t, %1; cvt.u32.u64 %0, t; }"
        : "=r"(a) : "l"(p));
    return a;
}

__device__ __forceinline__ void cpa16(uint32_t dst, const void* src) {
    asm volatile("cp.async.cg.shared.global [%0], [%1], 16;" :: "r"(dst), "l"(src) : "memory");
}
#define CP_COMMIT() asm volatile("cp.async.commit_group;" ::: "memory")
#define CP_WAIT1()  asm volatile("cp.async.wait_group 1;" ::: "memory")
#define CP_WAIT0()  asm volatile("cp.async.wait_group 0;" ::: "memory")

__device__ __forceinline__ void mma_bf16(float* c, const uint32_t* a, const uint32_t* b) {
    asm volatile(
        "mma.sync.aligned.m16n8k16.row.col.f32.bf16.bf16.f32 "
        "{%0,%1,%2,%3}, {%4,%5,%6,%7}, {%8,%9}, {%0,%1,%2,%3};"
        : "+f"(c[0]), "+f"(c[1]), "+f"(c[2]), "+f"(c[3])
        : "r"(a[0]), "r"(a[1]), "r"(a[2]), "r"(a[3]), "r"(b[0]), "r"(b[1]));
}

__device__ __forceinline__ void ldm_x4(uint32_t* r, uint32_t addr) {
    asm volatile("ldmatrix.sync.aligned.m8n8.x4.shared.b16 {%0,%1,%2,%3}, [%4];"
        : "=r"(r[0]), "=r"(r[1]), "=r"(r[2]), "=r"(r[3]) : "r"(addr));
}

__device__ __forceinline__ void split2(float v, __nv_bfloat16& h, __nv_bfloat16& l) {
    h = __float2bfloat16(v);
    l = __float2bfloat16(v - __bfloat162float(h));
}

__device__ __forceinline__ uint32_t packbf(__nv_bfloat16 a, __nv_bfloat16 b) {
    __nv_bfloat162 t(a, b);   // a = low element
    return *(uint32_t*)&t;
}

// ---------------------------------------------------------------------------
// LayerNorm -> bf16 hi/lo split outputs
// ---------------------------------------------------------------------------
__global__ __launch_bounds__(256) void ln_kernel(const float* __restrict__ x,
                                                 __nv_bfloat16* __restrict__ yh,
                                                 __nv_bfloat16* __restrict__ yl) {
    __shared__ float red_s[8], red_ss[8];
    __shared__ float sh_mu, sh_rstd;
    const int row = blockIdx.x;
    const int tid = threadIdx.x;
    const float* xr = x + (size_t)row * DD;

    float4 a = *(const float4*)(xr + tid * 4);
    float4 b = *(const float4*)(xr + 1024 + tid * 4);
    float s  = a.x + a.y + a.z + a.w + b.x + b.y + b.z + b.w;
    float ss = a.x*a.x + a.y*a.y + a.z*a.z + a.w*a.w
             + b.x*b.x + b.y*b.y + b.z*b.z + b.w*b.w;
    #pragma unroll
    for (int o = 16; o > 0; o >>= 1) {
        s  += __shfl_xor_sync(0xffffffffu, s, o);
        ss += __shfl_xor_sync(0xffffffffu, ss, o);
    }
    const int wid = tid >> 5, lane = tid & 31;
    if (lane == 0) { red_s[wid] = s; red_ss[wid] = ss; }
    __syncthreads();
    if (tid == 0) {
        float S = 0.f, SSq = 0.f;
        #pragma unroll
        for (int w = 0; w < 8; w++) { S += red_s[w]; SSq += red_ss[w]; }
        float mu = S * (1.0f / DD);
        float var = SSq * (1.0f / DD) - mu * mu;
        sh_mu = mu;
        sh_rstd = rsqrtf(var + LN_EPS);
    }
    __syncthreads();
    const float mu = sh_mu, rstd = sh_rstd;
    float va[8] = {a.x, a.y, a.z, a.w, b.x, b.y, b.z, b.w};
    #pragma unroll
    for (int e = 0; e < 8; e++) {
        float v = (va[e] - mu) * rstd;
        __nv_bfloat16 h, l;
        split2(v, h, l);
        size_t col = (e < 4) ? (tid * 4 + e) : (1024 + tid * 4 + e - 4);
        yh[(size_t)row * DD + col] = h;
        yl[(size_t)row * DD + col] = l;
    }
}

// ---------------------------------------------------------------------------
// Transpose + split: W[K][N] fp32 -> hi/lo bf16 [N][K]
// ---------------------------------------------------------------------------
__global__ __launch_bounds__(256) void transpose_split(const float* __restrict__ W,
                                                       __nv_bfloat16* __restrict__ hi,
                                                       __nv_bfloat16* __restrict__ lo,
                                                       int K, int N) {
    __shared__ float t[32][33];
    int n = blockIdx.x * 32 + threadIdx.x;
    int k = blockIdx.y * 32 + threadIdx.y;
    #pragma unroll
    for (int i = 0; i < 4; i++)
        t[threadIdx.y + 8 * i][threadIdx.x] = W[(size_t)(k + 8 * i) * N + n];
    __syncthreads();
    int ko = blockIdx.y * 32 + threadIdx.x;
    int no = blockIdx.x * 32 + threadIdx.y;
    #pragma unroll
    for (int i = 0; i < 4; i++) {
        float v = t[threadIdx.x][threadIdx.y + 8 * i];
        __nv_bfloat16 h, l;
        split2(v, h, l);
        size_t o = (size_t)(no + 8 * i) * K + ko;
        hi[o] = h;
        lo[o] = l;
    }
}

// ---------------------------------------------------------------------------
// mma.sync split-bf16 GEMM v3: C[M,N] fp32 = (Ahi+Alo)[M,K] @ (Bhi+Blo)[N,K]^T
// CTA tile 128x256, BK=32, 8 warps (2x4), warp tile 64x64.
// 3-stage cp.async ring, ONE __syncthreads per chunk, fill-before-compute.
// ---------------------------------------------------------------------------
#define BM 128
#define BN 256
#define BKC 32
#define ROWB 80                       // padded row bytes (32 bf16 = 64B data)
#define A_TILE (128 * ROWB)           // 10240
#define B_TILE (256 * ROWB)           // 20480
#define STAGE_B (2 * A_TILE + 2 * B_TILE)   // 61440
#define NSTAGE 3
#define GEMM_SMEM (NSTAGE * STAGE_B)        // 184320

__global__ __launch_bounds__(256, 1) void gemm_mma(
    const __nv_bfloat16* __restrict__ Ahi, const __nv_bfloat16* __restrict__ Alo,
    const __nv_bfloat16* __restrict__ Bhi, const __nv_bfloat16* __restrict__ Blo,
    float* __restrict__ C, int M, int N, int K)
{
    extern __shared__ __align__(16) char smem[];
    const uint32_t sb = smem_u32(smem);
    const int tid = threadIdx.x;
    const int wid = tid >> 5;
    const int lane = tid & 31;
    const int m0 = blockIdx.y * BM;
    const int n0 = blockIdx.x * BN;
    const int wm = (wid & 1) * 64;        // warp m offset (0 or 64)
    const int wn = (wid >> 1) * 64;       // warp n offset (0,64,128,192)

    float acc[4][8][4];
    #pragma unroll
    for (int mi = 0; mi < 4; mi++)
        #pragma unroll
        for (int ni = 0; ni < 8; ni++)
            #pragma unroll
            for (int e = 0; e < 4; e++) acc[mi][ni][e] = 0.f;

    auto fill = [&](int stage, int k0) {
        const uint32_t sbase = sb + stage * STAGE_B;
        #pragma unroll
        for (int it = 0; it < 12; it++) {
            int i = it * 256 + tid;               // 3072 x 16B chunks
            const __nv_bfloat16* src;
            uint32_t dst;
            if (i < 1024) {                        // A hi/lo: 2 x 128 rows x 4
                int op = i >> 9, r = (i >> 2) & 127, c = i & 3;
                src = (op ? Alo : Ahi) + (size_t)(m0 + r) * K + k0 + c * 8;
                dst = sbase + op * A_TILE + r * ROWB + c * 16;
            } else {                               // B hi/lo: 2 x 256 rows x 4
                int j = i - 1024;
                int op = j >> 10, r = (j >> 2) & 255, c = j & 3;
                src = (op ? Blo : Bhi) + (size_t)(n0 + r) * K + k0 + c * 8;
                dst = sbase + 2 * A_TILE + op * B_TILE + r * ROWB + c * 16;
            }
            cpa16(dst, src);
        }
        CP_COMMIT();
    };

    const int nch = K / BKC;     // 64
    fill(0, 0);
    fill(1, BKC);

    // ldmatrix lane-address components
    const int lg = lane >> 3;     // 0..3 (8-lane group)
    const int lr = lane & 7;      // row within group

    for (int c = 0; c < nch; c++) {
        // Stage c's copies must be complete. If c+1 fill exists it may stay
        // in flight (<=1 pending); otherwise drain fully.
        if (c + 1 < nch) CP_WAIT1(); else CP_WAIT0();
        __syncthreads();   // all warps done with chunk c-1; stage (c+2)%3 free

        // Prefetch stage c+2 BEFORE compute so the copy overlaps the MMAs.
        if (c + 2 < nch) fill((c + 2) % NSTAGE, (c + 2) * BKC);

        const uint32_t sbase = sb + (c % NSTAGE) * STAGE_B;
        const uint32_t aHi = sbase;
        const uint32_t aLo = sbase + A_TILE;
        const uint32_t bHi = sbase + 2 * A_TILE;
        const uint32_t bLo = sbase + 2 * A_TILE + B_TILE;

        #pragma unroll
        for (int ks = 0; ks < 2; ks++) {
            const uint32_t koff = ks * 32;

            const uint32_t aoff = (lg & 1) * 8 * ROWB + (lg >> 1) * 16 + lr * ROWB + koff;
            uint32_t ah[4][4], al[4][4];
            #pragma unroll
            for (int mi = 0; mi < 4; mi++) {
                uint32_t ro = (wm + mi * 16) * ROWB + aoff;
                ldm_x4(ah[mi], aHi + ro);
                ldm_x4(al[mi], aLo + ro);
            }
            const uint32_t boff = (lg >> 1) * 8 * ROWB + (lg & 1) * 16 + lr * ROWB + koff;
            uint32_t bh[8][2], bl[8][2];
            #pragma unroll
            for (int np = 0; np < 4; np++) {
                uint32_t ro = (wn + np * 16) * ROWB + boff;
                uint32_t t4[4];
                ldm_x4(t4, bHi + ro);
                bh[2 * np][0] = t4[0]; bh[2 * np][1] = t4[1];
                bh[2 * np + 1][0] = t4[2]; bh[2 * np + 1][1] = t4[3];
                ldm_x4(t4, bLo + ro);
                bl[2 * np][0] = t4[0]; bl[2 * np][1] = t4[1];
                bl[2 * np + 1][0] = t4[2]; bl[2 * np + 1][1] = t4[3];
            }

            #pragma unroll
            for (int mi = 0; mi < 4; mi++)
                #pragma unroll
                for (int ni = 0; ni < 8; ni++)
                    mma_bf16(acc[mi][ni], ah[mi], bh[ni]);
            #pragma unroll
            for (int mi = 0; mi < 4; mi++)
                #pragma unroll
                for (int ni = 0; ni < 8; ni++)
                    mma_bf16(acc[mi][ni], ah[mi], bl[ni]);
            #pragma unroll
            for (int mi = 0; mi < 4; mi++)
                #pragma unroll
                for (int ni = 0; ni < 8; ni++)
                    mma_bf16(acc[mi][ni], al[mi], bh[ni]);
        }
    }

    const int r4 = lane >> 2;
    const int k4 = lane & 3;
    #pragma unroll
    for (int mi = 0; mi < 4; mi++) {
        int r0 = m0 + wm + mi * 16 + r4;
        #pragma unroll
        for (int ni = 0; ni < 8; ni++) {
            int cc = n0 + wn + ni * 8 + k4 * 2;
            float2 v0 = {acc[mi][ni][0], acc[mi][ni][1]};
            float2 v1 = {acc[mi][ni][2], acc[mi][ni][3]};
            *(float2*)(C + (size_t)r0 * N + cc) = v0;
            *(float2*)(C + (size_t)(r0 + 8) * N + cc) = v1;
        }
    }
}

// ---------------------------------------------------------------------------
// RoPE (in place, fp32 qkv).  positions = arange(S) per batch.
// ---------------------------------------------------------------------------
__global__ __launch_bounds__(256) void rope_kernel(float* __restrict__ qkv) {
    const int idx = blockIdx.x * blockDim.x + threadIdx.x;
    if (idx >= NTOK * HH * 64) return;
    const int d = idx & 63;
    const int h = (idx >> 6) & 15;
    const int t = idx >> 10;

    const float pos = (float)(t % SS);
    const float inv_freq = powf(10000.0f, -(float)d * (1.0f / 64.0f));
    const float ang = pos * inv_freq;
    const float c = cosf(ang), s = sinf(ang);

    float* q = qkv + (size_t)t * QKV_N + h * DHH;
    float x1 = q[d], x2 = q[d + 64];
    q[d]      = x1 * c - x2 * s;
    q[d + 64] = x2 * c + x1 * s;

    float* k = q + DD;
    x1 = k[d]; x2 = k[d + 64];
    k[d]      = x1 * c - x2 * s;
    k[d + 64] = x2 * c + x1 * s;
}

// ---------------------------------------------------------------------------
// Flash attention v2 (unchanged — proven)
// ---------------------------------------------------------------------------
#define QROW 272
#define VROW 144
#define F2_QH 0
#define F2_QL (F2_QH + 64 * QROW)
#define F2_KH (F2_QL + 64 * QROW)
#define F2_KL (F2_KH + 64 * QROW)
#define F2_VH (F2_KL + 64 * QROW)
#define F2_VL (F2_VH + 128 * VROW)
#define FLASH2_SMEM (F2_VL + 128 * VROW)   // 106496 bytes

__global__ __launch_bounds__(128) void flash2_kernel(const float* __restrict__ qkv,
                                                     __nv_bfloat16* __restrict__ attn_hi,
                                                     __nv_bfloat16* __restrict__ attn_lo) {
    extern __shared__ __align__(16) char smem[];

    const int qb = blockIdx.x;
    const int h  = blockIdx.y;
    const int b  = blockIdx.z;
    const int tid = threadIdx.x;
    const int wid = tid >> 5;
    const int lane = tid & 31;
    const int r4 = lane >> 2;
    const int k4 = lane & 3;

    const float* qbase = qkv + (size_t)(b * SS) * QKV_N + h * DHH;
    const float* kbase = qbase + DD;
    const float* vbase = qbase + 2 * DD;

    for (int i = tid; i < 64 * 32; i += 128) {
        int row = i >> 5, d4 = (i & 31) * 4;
        float4 v = *(const float4*)(qbase + (size_t)(qb * 64 + row) * QKV_N + d4);
        __nv_bfloat16 h0,l0,h1,l1,h2,l2,h3,l3;
        split2(v.x, h0, l0); split2(v.y, h1, l1);
        split2(v.z, h2, l2); split2(v.w, h3, l3);
        uint32_t off = row * QROW + d4 * 2;
        *(uint32_t*)(smem + F2_QH + off)     = packbf(h0, h1);
        *(uint32_t*)(smem + F2_QH + off + 4) = packbf(h2, h3);
        *(uint32_t*)(smem + F2_QL + off)     = packbf(l0, l1);
        *(uint32_t*)(smem + F2_QL + off + 4) = packbf(l2, l3);
    }

    float oacc[16][4];
    #pragma unroll
    for (int n = 0; n < 16; n++)
        #pragma unroll
        for (int e = 0; e < 4; e++) oacc[n][e] = 0.f;

    float m0 = -1e30f, m1 = -1e30f, l0 = 0.f, l1 = 0.f;
    const float scale = 0.088388347648318447f;
    const int arow = wid * 16 + r4;

    for (int kt = 0; kt <= qb; kt++) {
        __syncthreads();
        for (int i = tid; i < 64 * 32; i += 128) {
            int row = i >> 5, d4 = (i & 31) * 4;
            float4 v = *(const float4*)(kbase + (size_t)(kt * 64 + row) * QKV_N + d4);
            __nv_bfloat16 h0,ll0,h1,ll1,h2,ll2,h3,ll3;
            split2(v.x, h0, ll0); split2(v.y, h1, ll1);
            split2(v.z, h2, ll2); split2(v.w, h3, ll3);
            uint32_t off = row * QROW + d4 * 2;
            *(uint32_t*)(smem + F2_KH + off)     = packbf(h0, h1);
            *(uint32_t*)(smem + F2_KH + off + 4) = packbf(h2, h3);
            *(uint32_t*)(smem + F2_KL + off)     = packbf(ll0, ll1);
            *(uint32_t*)(smem + F2_KL + off + 4) = packbf(ll2, ll3);
        }
        {
            const float* vcol = vbase + tid;
            #pragma unroll 4
            for (int kk = 0; kk < 64; kk += 2) {
                float v0 = vcol[(size_t)(kt * 64 + kk) * QKV_N];
                float v1 = vcol[(size_t)(kt * 64 + kk + 1) * QKV_N];
                __nv_bfloat16 h0,ll0,h1,ll1;
                split2(v0, h0, ll0); split2(v1, h1, ll1);
                *(uint32_t*)(smem + F2_VH + tid * VROW + kk * 2) = packbf(h0, h1);
                *(uint32_t*)(smem + F2_VL + tid * VROW + kk * 2) = packbf(ll0, ll1);
            }
        }
        __syncthreads();

        float sacc[8][4];
        #pragma unroll
        for (int n = 0; n < 8; n++)
            #pragma unroll
            for (int e = 0; e < 4; e++) sacc[n][e] = 0.f;

        #pragma unroll
        for (int kb = 0; kb < 8; kb++) {
            const uint32_t koff = kb * 32 + k4 * 4;
            uint32_t ah[4], al[4];
            ah[0] = *(const uint32_t*)(smem + F2_QH + arow * QROW + koff);
            ah[1] = *(const uint32_t*)(smem + F2_QH + (arow + 8) * QROW + koff);
            ah[2] = *(const uint32_t*)(smem + F2_QH + arow * QROW + koff + 16);
            ah[3] = *(const uint32_t*)(smem + F2_QH + (arow + 8) * QROW + koff + 16);
            al[0] = *(const uint32_t*)(smem + F2_QL + arow * QROW + koff);
            al[1] = *(const uint32_t*)(smem + F2_QL + (arow + 8) * QROW + koff);
            al[2] = *(const uint32_t*)(smem + F2_QL + arow * QROW + koff + 16);
            al[3] = *(const uint32_t*)(smem + F2_QL + (arow + 8) * QROW + koff + 16);
            #pragma unroll
            for (int ng = 0; ng < 8; ng++) {
                const uint32_t bro = (ng * 8 + r4) * QROW + koff;
                uint32_t bh[2], bl[2];
                bh[0] = *(const uint32_t*)(smem + F2_KH + bro);
                bh[1] = *(const uint32_t*)(smem + F2_KH + bro + 16);
                bl[0] = *(const uint32_t*)(smem + F2_KL + bro);
                bl[1] = *(const uint32_t*)(smem + F2_KL + bro + 16);
                mma_bf16(sacc[ng], ah, bh);
                mma_bf16(sacc[ng], ah, bl);
                mma_bf16(sacc[ng], al, bh);
            }
        }

        const int row0 = qb * 64 + wid * 16 + r4;
        if (kt == qb) {
            #pragma unroll
            for (int ng = 0; ng < 8; ng++) {
                int colb = kt * 64 + ng * 8 + k4 * 2;
                sacc[ng][0] = (colb     > row0)     ? -1e30f : sacc[ng][0] * scale;
                sacc[ng][1] = (colb + 1 > row0)     ? -1e30f : sacc[ng][1] * scale;
                sacc[ng][2] = (colb     > row0 + 8) ? -1e30f : sacc[ng][2] * scale;
                sacc[ng][3] = (colb + 1 > row0 + 8) ? -1e30f : sacc[ng][3] * scale;
            }
        } else {
            #pragma unroll
            for (int ng = 0; ng < 8; ng++)
                #pragma unroll
                for (int e = 0; e < 4; e++) sacc[ng][e] *= scale;
        }

        float mx0 = -1e30f, mx1 = -1e30f;
        #pragma unroll
        for (int ng = 0; ng < 8; ng++) {
            mx0 = fmaxf(mx0, fmaxf(sacc[ng][0], sacc[ng][1]));
            mx1 = fmaxf(mx1, fmaxf(sacc[ng][2], sacc[ng][3]));
        }
        mx0 = fmaxf(mx0, __shfl_xor_sync(0xffffffffu, mx0, 1));
        mx0 = fmaxf(mx0, __shfl_xor_sync(0xffffffffu, mx0, 2));
        mx1 = fmaxf(mx1, __shfl_xor_sync(0xffffffffu, mx1, 1));
        mx1 = fmaxf(mx1, __shfl_xor_sync(0xffffffffu, mx1, 2));

        float mn0 = fmaxf(m0, mx0), mn1 = fmaxf(m1, mx1);
        float c0 = __expf(m0 - mn0), c1 = __expf(m1 - mn1);
        m0 = mn0; m1 = mn1;

        float sum0 = 0.f, sum1 = 0.f;
        uint32_t ph2[8][2], pl2[8][2];
        #pragma unroll
        for (int ng = 0; ng < 8; ng++) {
            float p0 = __expf(sacc[ng][0] - m0);
            float p1 = __expf(sacc[ng][1] - m0);
            float p2 = __expf(sacc[ng][2] - m1);
            float p3 = __expf(sacc[ng][3] - m1);
            sum0 += p0 + p1; sum1 += p2 + p3;
            __nv_bfloat16 a,bq,cc,dd2, la,lb,lc,ld;
            split2(p0, a, la); split2(p1, bq, lb);
            split2(p2, cc, lc); split2(p3, dd2, ld);
            ph2[ng][0] = packbf(a, bq);  ph2[ng][1] = packbf(cc, dd2);
            pl2[ng][0] = packbf(la, lb); pl2[ng][1] = packbf(lc, ld);
        }
        sum0 += __shfl_xor_sync(0xffffffffu, sum0, 1);
        sum0 += __shfl_xor_sync(0xffffffffu, sum0, 2);
        sum1 += __shfl_xor_sync(0xffffffffu, sum1, 1);
        sum1 += __shfl_xor_sync(0xffffffffu, sum1, 2);
        l0 = l0 * c0 + sum0;
        l1 = l1 * c1 + sum1;

        #pragma unroll
        for (int n = 0; n < 16; n++) {
            oacc[n][0] *= c0; oacc[n][1] *= c0;
            oacc[n][2] *= c1; oacc[n][3] *= c1;
        }

        #pragma unroll
        for (int kb = 0; kb < 4; kb++) {
            uint32_t pa[4] = {ph2[2*kb][0], ph2[2*kb][1], ph2[2*kb+1][0], ph2[2*kb+1][1]};
            uint32_t pb[4] = {pl2[2*kb][0], pl2[2*kb][1], pl2[2*kb+1][0], pl2[2*kb+1][1]};
            const uint32_t koff = kb * 32 + k4 * 4;
            #pragma unroll
            for (int ng = 0; ng < 16; ng++) {
                const uint32_t vro = (ng * 8 + r4) * VROW + koff;
                uint32_t vh[2], vl[2];
                vh[0] = *(const uint32_t*)(smem + F2_VH + vro);
                vh[1] = *(const uint32_t*)(smem + F2_VH + vro + 16);
                vl[0] = *(const uint32_t*)(smem + F2_VL + vro);
                vl[1] = *(const uint32_t*)(smem + F2_VL + vro + 16);
                mma_bf16(oacc[ng], pa, vh);
                mma_bf16(oacc[ng], pa, vl);
                mma_bf16(oacc[ng], pb, vh);
            }
        }
    }

    const float inv0 = 1.0f / l0, inv1 = 1.0f / l1;
    const int grow0 = b * SS + qb * 64 + wid * 16 + r4;
    #pragma unroll
    for (int ng = 0; ng < 16; ng++) {
        size_t o0 = (size_t)grow0 * DD + h * DHH + ng * 8 + k4 * 2;
        size_t o1 = o0 + (size_t)8 * DD;
        float v0 = oacc[ng][0] * inv0, v1 = oacc[ng][1] * inv0;
        float v2 = oacc[ng][2] * inv1, v3 = oacc[ng][3] * inv1;
        __nv_bfloat16 h0,l0b,h1,l1b,h2,l2b,h3,l3b;
        split2(v0, h0, l0b); split2(v1, h1, l1b);
        split2(v2, h2, l2b); split2(v3, h3, l3b);
        *(uint32_t*)(attn_hi + o0) = packbf(h0, h1);
        *(uint32_t*)(attn_lo + o0) = packbf(l0b, l1b);
        *(uint32_t*)(attn_hi + o1) = packbf(h2, h3);
        *(uint32_t*)(attn_lo + o1) = packbf(l2b, l3b);
    }
}

// ---------------------------------------------------------------------------
// kernel_launch: inputs = [positions, hidden_states, w_qkv, w_out]
// ---------------------------------------------------------------------------
extern "C" void kernel_launch(void* const* d_in, const int* in_sizes, int n_in,
                              void* d_out, int out_size) {
    const float* hidden = (const float*)d_in[1];
    const float* w_qkv  = (const float*)d_in[2];
    const float* w_out  = (const float*)d_in[3];
    float* out = (float*)d_out;

    __nv_bfloat16 *xh, *xl, *wqh, *wql, *woh, *wol, *ah, *al;
    float* qkv;
    cudaGetSymbolAddress((void**)&xh,  g_xln_hi);
    cudaGetSymbolAddress((void**)&xl,  g_xln_lo);
    cudaGetSymbolAddress((void**)&qkv, g_qkv);
    cudaGetSymbolAddress((void**)&wqh, g_wqkvT_hi);
    cudaGetSymbolAddress((void**)&wql, g_wqkvT_lo);
    cudaGetSymbolAddress((void**)&woh, g_woutT_hi);
    cudaGetSymbolAddress((void**)&wol, g_woutT_lo);
    cudaGetSymbolAddress((void**)&ah,  g_attn_hi);
    cudaGetSymbolAddress((void**)&al,  g_attn_lo);

    // 1) LayerNorm -> split bf16
    ln_kernel<<<NTOK, 256>>>(hidden, xh, xl);

    // 2) Weight transpose+split
    dim3 tb(32, 8);
    transpose_split<<<dim3(QKV_N / 32, DD / 32), tb>>>(w_qkv, wqh, wql, DD, QKV_N);
    transpose_split<<<dim3(DD / 32, DD / 32), tb>>>(w_out, woh, wol, DD, DD);

    // 3) QKV projection (tensor cores via mma.sync)
    cudaFuncSetAttribute(gemm_mma, cudaFuncAttributeMaxDynamicSharedMemorySize, GEMM_SMEM);
    gemm_mma<<<dim3(QKV_N / BN, NTOK / BM), 256, GEMM_SMEM>>>(
        xh, xl, wqh, wql, qkv, NTOK, QKV_N, DD);

    // 4) RoPE
    rope_kernel<<<(NTOK * HH * 64 + 255) / 256, 256>>>(qkv);

    // 5) Causal flash attention v2 (tensor cores) -> split bf16
    cudaFuncSetAttribute(flash2_kernel, cudaFuncAttributeMaxDynamicSharedMemorySize,
                         FLASH2_SMEM);
    flash2_kernel<<<dim3(SS / 64, HH, BB), 128, FLASH2_SMEM>>>(qkv, ah, al);

    // 6) Output projection (tensor cores via mma.sync)
    gemm_mma<<<dim3(DD / BN, NTOK / BM), 256, GEMM_SMEM>>>(
        ah, al, woh, wol, out, NTOK, DD, DD);
}

// round 7
// speedup vs baseline: 2.9356x; 1.1340x over previous
#include <cuda_runtime.h>
#include <cuda_bf16.h>
#include <math.h>
#include <cstdint>

// ---------------------------------------------------------------------------
// Problem constants: B=2, S=2048, D=2048, H=16, DH=128
// ---------------------------------------------------------------------------
#define BB 2
#define SS 2048
#define DD 2048
#define HH 16
#define DHH 128
#define NTOK (BB * SS)          // 4096
#define QKV_N (3 * DD)          // 6144
#define LN_EPS 1e-5f

// ---------------------------------------------------------------------------
// Scratch (device globals; allocation forbidden)
// ---------------------------------------------------------------------------
__device__ __nv_bfloat16 g_xln_hi[(size_t)NTOK * DD];
__device__ __nv_bfloat16 g_xln_lo[(size_t)NTOK * DD];
__device__ float         g_qkv[(size_t)NTOK * QKV_N];     // 100.7 MB
__device__ __nv_bfloat16 g_wqkvT_hi[(size_t)QKV_N * DD];
__device__ __nv_bfloat16 g_wqkvT_lo[(size_t)QKV_N * DD];
__device__ __nv_bfloat16 g_woutT_hi[(size_t)DD * DD];
__device__ __nv_bfloat16 g_woutT_lo[(size_t)DD * DD];
__device__ __nv_bfloat16 g_attn_hi[(size_t)NTOK * DD];
__device__ __nv_bfloat16 g_attn_lo[(size_t)NTOK * DD];
// pre-split attention operands, per-head layouts
__device__ __nv_bfloat16 g_qh[(size_t)NTOK * DD];   // [b][h][s][d]
__device__ __nv_bfloat16 g_ql[(size_t)NTOK * DD];
__device__ __nv_bfloat16 g_kh[(size_t)NTOK * DD];
__device__ __nv_bfloat16 g_kl[(size_t)NTOK * DD];
__device__ __nv_bfloat16 g_vth[(size_t)NTOK * DD];  // [b][h][d][s]
__device__ __nv_bfloat16 g_vtl[(size_t)NTOK * DD];

// ---------------------------------------------------------------------------
// helpers
// ---------------------------------------------------------------------------
__device__ __forceinline__ uint32_t smem_u32(const void* p) {
    uint32_t a;
    asm("{ .reg .u64 t; cvta.to.shared.u64 t, %1; cvt.u32.u64 %0, t; }"
        : "=r"(a) : "l"(p));
    return a;
}

__device__ __forceinline__ void cpa16(uint32_t dst, const void* src) {
    asm volatile("cp.async.cg.shared.global [%0], [%1], 16;" :: "r"(dst), "l"(src) : "memory");
}
#define CP_COMMIT() asm volatile("cp.async.commit_group;" ::: "memory")
#define CP_WAIT1()  asm volatile("cp.async.wait_group 1;" ::: "memory")
#define CP_WAIT0()  asm volatile("cp.async.wait_group 0;" ::: "memory")

__device__ __forceinline__ void mma_bf16(float* c, const uint32_t* a, const uint32_t* b) {
    asm volatile(
        "mma.sync.aligned.m16n8k16.row.col.f32.bf16.bf16.f32 "
        "{%0,%1,%2,%3}, {%4,%5,%6,%7}, {%8,%9}, {%0,%1,%2,%3};"
        : "+f"(c[0]), "+f"(c[1]), "+f"(c[2]), "+f"(c[3])
        : "r"(a[0]), "r"(a[1]), "r"(a[2]), "r"(a[3]), "r"(b[0]), "r"(b[1]));
}

__device__ __forceinline__ void ldm_x4(uint32_t* r, uint32_t addr) {
    asm volatile("ldmatrix.sync.aligned.m8n8.x4.shared.b16 {%0,%1,%2,%3}, [%4];"
        : "=r"(r[0]), "=r"(r[1]), "=r"(r[2]), "=r"(r[3]) : "r"(addr));
}

__device__ __forceinline__ void split2(float v, __nv_bfloat16& h, __nv_bfloat16& l) {
    h = __float2bfloat16(v);
    l = __float2bfloat16(v - __bfloat162float(h));
}

__device__ __forceinline__ uint32_t packbf(__nv_bfloat16 a, __nv_bfloat16 b) {
    __nv_bfloat162 t(a, b);   // a = low element
    return *(uint32_t*)&t;
}

// ---------------------------------------------------------------------------
// LayerNorm -> bf16 hi/lo split outputs
// ---------------------------------------------------------------------------
__global__ __launch_bounds__(256) void ln_kernel(const float* __restrict__ x,
                                                 __nv_bfloat16* __restrict__ yh,
                                                 __nv_bfloat16* __restrict__ yl) {
    __shared__ float red_s[8], red_ss[8];
    __shared__ float sh_mu, sh_rstd;
    const int row = blockIdx.x;
    const int tid = threadIdx.x;
    const float* xr = x + (size_t)row * DD;

    float4 a = *(const float4*)(xr + tid * 4);
    float4 b = *(const float4*)(xr + 1024 + tid * 4);
    float s  = a.x + a.y + a.z + a.w + b.x + b.y + b.z + b.w;
    float ss = a.x*a.x + a.y*a.y + a.z*a.z + a.w*a.w
             + b.x*b.x + b.y*b.y + b.z*b.z + b.w*b.w;
    #pragma unroll
    for (int o = 16; o > 0; o >>= 1) {
        s  += __shfl_xor_sync(0xffffffffu, s, o);
        ss += __shfl_xor_sync(0xffffffffu, ss, o);
    }
    const int wid = tid >> 5, lane = tid & 31;
    if (lane == 0) { red_s[wid] = s; red_ss[wid] = ss; }
    __syncthreads();
    if (tid == 0) {
        float S = 0.f, SSq = 0.f;
        #pragma unroll
        for (int w = 0; w < 8; w++) { S += red_s[w]; SSq += red_ss[w]; }
        float mu = S * (1.0f / DD);
        float var = SSq * (1.0f / DD) - mu * mu;
        sh_mu = mu;
        sh_rstd = rsqrtf(var + LN_EPS);
    }
    __syncthreads();
    const float mu = sh_mu, rstd = sh_rstd;
    float va[8] = {a.x, a.y, a.z, a.w, b.x, b.y, b.z, b.w};
    #pragma unroll
    for (int e = 0; e < 8; e++) {
        float v = (va[e] - mu) * rstd;
        __nv_bfloat16 h, l;
        split2(v, h, l);
        size_t col = (e < 4) ? (tid * 4 + e) : (1024 + tid * 4 + e - 4);
        yh[(size_t)row * DD + col] = h;
        yl[(size_t)row * DD + col] = l;
    }
}

// ---------------------------------------------------------------------------
// Transpose + split: W[K][N] fp32 -> hi/lo bf16 [N][K]
// ---------------------------------------------------------------------------
__global__ __launch_bounds__(256) void transpose_split(const float* __restrict__ W,
                                                       __nv_bfloat16* __restrict__ hi,
                                                       __nv_bfloat16* __restrict__ lo,
                                                       int K, int N) {
    __shared__ float t[32][33];
    int n = blockIdx.x * 32 + threadIdx.x;
    int k = blockIdx.y * 32 + threadIdx.y;
    #pragma unroll
    for (int i = 0; i < 4; i++)
        t[threadIdx.y + 8 * i][threadIdx.x] = W[(size_t)(k + 8 * i) * N + n];
    __syncthreads();
    int ko = blockIdx.y * 32 + threadIdx.x;
    int no = blockIdx.x * 32 + threadIdx.y;
    #pragma unroll
    for (int i = 0; i < 4; i++) {
        float v = t[threadIdx.x][threadIdx.y + 8 * i];
        __nv_bfloat16 h, l;
        split2(v, h, l);
        size_t o = (size_t)(no + 8 * i) * K + ko;
        hi[o] = h;
        lo[o] = l;
    }
}

// ---------------------------------------------------------------------------
// mma.sync split-bf16 GEMM v3 (unchanged from round 6)
// ---------------------------------------------------------------------------
#define BM 128
#define BN 256
#define BKC 32
#define ROWB 80
#define A_TILE (128 * ROWB)
#define B_TILE (256 * ROWB)
#define STAGE_B (2 * A_TILE + 2 * B_TILE)
#define NSTAGE 3
#define GEMM_SMEM (NSTAGE * STAGE_B)

__global__ __launch_bounds__(256, 1) void gemm_mma(
    const __nv_bfloat16* __restrict__ Ahi, const __nv_bfloat16* __restrict__ Alo,
    const __nv_bfloat16* __restrict__ Bhi, const __nv_bfloat16* __restrict__ Blo,
    float* __restrict__ C, int M, int N, int K)
{
    extern __shared__ __align__(16) char smem[];
    const uint32_t sb = smem_u32(smem);
    const int tid = threadIdx.x;
    const int wid = tid >> 5;
    const int lane = tid & 31;
    const int m0 = blockIdx.y * BM;
    const int n0 = blockIdx.x * BN;
    const int wm = (wid & 1) * 64;
    const int wn = (wid >> 1) * 64;

    float acc[4][8][4];
    #pragma unroll
    for (int mi = 0; mi < 4; mi++)
        #pragma unroll
        for (int ni = 0; ni < 8; ni++)
            #pragma unroll
            for (int e = 0; e < 4; e++) acc[mi][ni][e] = 0.f;

    auto fill = [&](int stage, int k0) {
        const uint32_t sbase = sb + stage * STAGE_B;
        #pragma unroll
        for (int it = 0; it < 12; it++) {
            int i = it * 256 + tid;
            const __nv_bfloat16* src;
            uint32_t dst;
            if (i < 1024) {
                int op = i >> 9, r = (i >> 2) & 127, c = i & 3;
                src = (op ? Alo : Ahi) + (size_t)(m0 + r) * K + k0 + c * 8;
                dst = sbase + op * A_TILE + r * ROWB + c * 16;
            } else {
                int j = i - 1024;
                int op = j >> 10, r = (j >> 2) & 255, c = j & 3;
                src = (op ? Blo : Bhi) + (size_t)(n0 + r) * K + k0 + c * 8;
                dst = sbase + 2 * A_TILE + op * B_TILE + r * ROWB + c * 16;
            }
            cpa16(dst, src);
        }
        CP_COMMIT();
    };

    const int nch = K / BKC;
    fill(0, 0);
    fill(1, BKC);

    const int lg = lane >> 3;
    const int lr = lane & 7;

    for (int c = 0; c < nch; c++) {
        if (c + 1 < nch) CP_WAIT1(); else CP_WAIT0();
        __syncthreads();

        if (c + 2 < nch) fill((c + 2) % NSTAGE, (c + 2) * BKC);

        const uint32_t sbase = sb + (c % NSTAGE) * STAGE_B;
        const uint32_t aHi = sbase;
        const uint32_t aLo = sbase + A_TILE;
        const uint32_t bHi = sbase + 2 * A_TILE;
        const uint32_t bLo = sbase + 2 * A_TILE + B_TILE;

        #pragma unroll
        for (int ks = 0; ks < 2; ks++) {
            const uint32_t koff = ks * 32;

            const uint32_t aoff = (lg & 1) * 8 * ROWB + (lg >> 1) * 16 + lr * ROWB + koff;
            uint32_t ah[4][4], al[4][4];
            #pragma unroll
            for (int mi = 0; mi < 4; mi++) {
                uint32_t ro = (wm + mi * 16) * ROWB + aoff;
                ldm_x4(ah[mi], aHi + ro);
                ldm_x4(al[mi], aLo + ro);
            }
            const uint32_t boff = (lg >> 1) * 8 * ROWB + (lg & 1) * 16 + lr * ROWB + koff;
            uint32_t bh[8][2], bl[8][2];
            #pragma unroll
            for (int np = 0; np < 4; np++) {
                uint32_t ro = (wn + np * 16) * ROWB + boff;
                uint32_t t4[4];
                ldm_x4(t4, bHi + ro);
                bh[2 * np][0] = t4[0]; bh[2 * np][1] = t4[1];
                bh[2 * np + 1][0] = t4[2]; bh[2 * np + 1][1] = t4[3];
                ldm_x4(t4, bLo + ro);
                bl[2 * np][0] = t4[0]; bl[2 * np][1] = t4[1];
                bl[2 * np + 1][0] = t4[2]; bl[2 * np + 1][1] = t4[3];
            }

            #pragma unroll
            for (int mi = 0; mi < 4; mi++)
                #pragma unroll
                for (int ni = 0; ni < 8; ni++)
                    mma_bf16(acc[mi][ni], ah[mi], bh[ni]);
            #pragma unroll
            for (int mi = 0; mi < 4; mi++)
                #pragma unroll
                for (int ni = 0; ni < 8; ni++)
                    mma_bf16(acc[mi][ni], ah[mi], bl[ni]);
            #pragma unroll
            for (int mi = 0; mi < 4; mi++)
                #pragma unroll
                for (int ni = 0; ni < 8; ni++)
                    mma_bf16(acc[mi][ni], al[mi], bh[ni]);
        }
    }

    const int r4 = lane >> 2;
    const int k4 = lane & 3;
    #pragma unroll
    for (int mi = 0; mi < 4; mi++) {
        int r0 = m0 + wm + mi * 16 + r4;
        #pragma unroll
        for (int ni = 0; ni < 8; ni++) {
            int cc = n0 + wn + ni * 8 + k4 * 2;
            float2 v0 = {acc[mi][ni][0], acc[mi][ni][1]};
            float2 v1 = {acc[mi][ni][2], acc[mi][ni][3]};
            *(float2*)(C + (size_t)r0 * N + cc) = v0;
            *(float2*)(C + (size_t)(r0 + 8) * N + cc) = v1;
        }
    }
}

// ---------------------------------------------------------------------------
// RoPE + split for Q,K: fp32 qkv -> per-head K-major bf16 hi/lo [b][h][s][d]
// ---------------------------------------------------------------------------
__global__ __launch_bounds__(256) void rope_split(const float* __restrict__ qkv,
                                                  __nv_bfloat16* __restrict__ qh,
                                                  __nv_bfloat16* __restrict__ ql,
                                                  __nv_bfloat16* __restrict__ kh,
                                                  __nv_bfloat16* __restrict__ kl) {
    const int t = blockIdx.x;            // token
    const int b = t / SS, s = t % SS;
    const int tid = threadIdx.x;

    #pragma unroll
    for (int w = 0; w < 4; w++) {
        int idx = w * 256 + tid;          // (h, dpair)
        int h = idx >> 6, dp = idx & 63;

        float inv_freq = powf(10000.0f, -(float)dp * (1.0f / 64.0f));
        float ang = (float)s * inv_freq;
        float c = cosf(ang), sn = sinf(ang);

        const float* src = qkv + (size_t)t * QKV_N + h * DHH;
        size_t obase = ((size_t)(b * HH + h) * SS + s) * DHH;
        __nv_bfloat16 hh, ll;

        // q
        float x1 = src[dp], x2 = src[dp + 64];
        float r1 = x1 * c - x2 * sn;
        float r2 = x2 * c + x1 * sn;
        split2(r1, hh, ll); qh[obase + dp] = hh;      ql[obase + dp] = ll;
        split2(r2, hh, ll); qh[obase + dp + 64] = hh; ql[obase + dp + 64] = ll;

        // k
        x1 = src[DD + dp]; x2 = src[DD + dp + 64];
        r1 = x1 * c - x2 * sn;
        r2 = x2 * c + x1 * sn;
        split2(r1, hh, ll); kh[obase + dp] = hh;      kl[obase + dp] = ll;
        split2(r2, hh, ll); kh[obase + dp + 64] = hh; kl[obase + dp + 64] = ll;
    }
}

// ---------------------------------------------------------------------------
// V transpose + split: fp32 qkv v-slice -> [b][h][d][s] bf16 hi/lo
// block: 64 s x 128 d tile
// ---------------------------------------------------------------------------
__global__ __launch_bounds__(256) void v_split_transpose(const float* __restrict__ qkv,
                                                         __nv_bfloat16* __restrict__ vth,
                                                         __nv_bfloat16* __restrict__ vtl) {
    __shared__ float sm[64 * 132];
    const int s0 = blockIdx.x * 64;
    const int h  = blockIdx.y;
    const int b  = blockIdx.z;
    const int tid = threadIdx.x;

    #pragma unroll
    for (int i = 0; i < 32; i++) {
        int idx = i * 256 + tid;
        int sl = idx >> 7, d = idx & 127;
        sm[sl * 132 + d] = qkv[((size_t)(b * SS + s0 + sl)) * QKV_N + 2 * DD + h * DHH + d];
    }
    __syncthreads();

    const int d = tid >> 1;
    const int sh = (tid & 1) * 32;
    size_t row = ((size_t)(b * HH + h) * DHH + d) * SS + s0 + sh;
    #pragma unroll
    for (int j = 0; j < 32; j += 2) {
        float v0 = sm[(sh + j) * 132 + d];
        float v1 = sm[(sh + j + 1) * 132 + d];
        __nv_bfloat16 h0, l0, h1, l1;
        split2(v0, h0, l0); split2(v1, h1, l1);
        *(uint32_t*)(vth + row + j) = packbf(h0, h1);
        *(uint32_t*)(vtl + row + j) = packbf(l0, l1);
    }
}

// ---------------------------------------------------------------------------
// Flash attention v3: pre-split bf16 inputs, cp.async tiles, 2 CTAs/SM.
// MMA core identical to proven flash2.
// ---------------------------------------------------------------------------
#define QROW 272
#define VROW 144
#define F2_QH 0
#define F2_QL (F2_QH + 64 * QROW)
#define F2_KH (F2_QL + 64 * QROW)
#define F2_KL (F2_KH + 64 * QROW)
#define F2_VH (F2_KL + 64 * QROW)
#define F2_VL (F2_VH + 128 * VROW)
#define FLASH2_SMEM (F2_VL + 128 * VROW)   // 106496 bytes -> 2 CTAs/SM

__global__ __launch_bounds__(128) void flash3_kernel(
    const __nv_bfloat16* __restrict__ qh, const __nv_bfloat16* __restrict__ ql,
    const __nv_bfloat16* __restrict__ kh, const __nv_bfloat16* __restrict__ kl,
    const __nv_bfloat16* __restrict__ vth, const __nv_bfloat16* __restrict__ vtl,
    __nv_bfloat16* __restrict__ attn_hi, __nv_bfloat16* __restrict__ attn_lo)
{
    extern __shared__ __align__(16) char smem[];
    const uint32_t sb = smem_u32(smem);

    const int qb = blockIdx.x;
    const int h  = blockIdx.y;
    const int b  = blockIdx.z;
    const int tid = threadIdx.x;
    const int wid = tid >> 5;
    const int lane = tid & 31;
    const int r4 = lane >> 2;
    const int k4 = lane & 3;

    const size_t bh = (size_t)(b * HH + h);
    const __nv_bfloat16* qhp = qh + (bh * SS + qb * 64) * DHH;
    const __nv_bfloat16* qlp = ql + (bh * SS + qb * 64) * DHH;

    // ---- load Q tile (bf16, pre-split) ----
    for (int i = tid; i < 2048; i += 128) {
        int op = i >> 10, j = i & 1023;
        int row = j >> 4, c = j & 15;
        const __nv_bfloat16* src = (op ? qlp : qhp) + row * DHH + c * 8;
        uint4 v = *(const uint4*)src;
        *(uint4*)(smem + (op ? F2_QL : F2_QH) + row * QROW + c * 16) = v;
    }

    float oacc[16][4];
    #pragma unroll
    for (int n = 0; n < 16; n++)
        #pragma unroll
        for (int e = 0; e < 4; e++) oacc[n][e] = 0.f;

    float m0 = -1e30f, m1 = -1e30f, l0 = 0.f, l1 = 0.f;
    const float scale = 0.088388347648318447f;
    const int arow = wid * 16 + r4;

    for (int kt = 0; kt <= qb; kt++) {
        __syncthreads();   // previous iteration done with K/V tiles

        // ---- async-load K and VT tiles (pre-split bf16) ----
        {
            const __nv_bfloat16* khp = kh + (bh * SS + kt * 64) * DHH;
            const __nv_bfloat16* klp = kl + (bh * SS + kt * 64) * DHH;
            const __nv_bfloat16* vhp = vth + bh * DHH * SS + kt * 64;
            const __nv_bfloat16* vlp = vtl + bh * DHH * SS + kt * 64;
            #pragma unroll
            for (int it = 0; it < 32; it++) {
                int i = it * 128 + tid;   // 4096 chunks
                if (i < 2048) {
                    int op = i >> 10, j = i & 1023;
                    int row = j >> 4, c = j & 15;
                    cpa16(sb + (op ? F2_KL : F2_KH) + row * QROW + c * 16,
                          (op ? klp : khp) + row * DHH + c * 8);
                } else {
                    int i2 = i - 2048;
                    int op = i2 >> 10, j = i2 & 1023;
                    int d = j >> 3, c = j & 7;
                    cpa16(sb + (op ? F2_VL : F2_VH) + d * VROW + c * 16,
                          (op ? vlp : vhp) + (size_t)d * SS + c * 8);
                }
            }
            CP_COMMIT();
        }
        CP_WAIT0();
        __syncthreads();

        // ---- S = Q K^T (split 3-term) ----
        float sacc[8][4];
        #pragma unroll
        for (int n = 0; n < 8; n++)
            #pragma unroll
            for (int e = 0; e < 4; e++) sacc[n][e] = 0.f;

        #pragma unroll
        for (int kb = 0; kb < 8; kb++) {
            const uint32_t koff = kb * 32 + k4 * 4;
            uint32_t ah[4], al[4];
            ah[0] = *(const uint32_t*)(smem + F2_QH + arow * QROW + koff);
            ah[1] = *(const uint32_t*)(smem + F2_QH + (arow + 8) * QROW + koff);
            ah[2] = *(const uint32_t*)(smem + F2_QH + arow * QROW + koff + 16);
            ah[3] = *(const uint32_t*)(smem + F2_QH + (arow + 8) * QROW + koff + 16);
            al[0] = *(const uint32_t*)(smem + F2_QL + arow * QROW + koff);
            al[1] = *(const uint32_t*)(smem + F2_QL + (arow + 8) * QROW + koff);
            al[2] = *(const uint32_t*)(smem + F2_QL + arow * QROW + koff + 16);
            al[3] = *(const uint32_t*)(smem + F2_QL + (arow + 8) * QROW + koff + 16);
            #pragma unroll
            for (int ng = 0; ng < 8; ng++) {
                const uint32_t bro = (ng * 8 + r4) * QROW + koff;
                uint32_t bh2[2], bl2[2];
                bh2[0] = *(const uint32_t*)(smem + F2_KH + bro);
                bh2[1] = *(const uint32_t*)(smem + F2_KH + bro + 16);
                bl2[0] = *(const uint32_t*)(smem + F2_KL + bro);
                bl2[1] = *(const uint32_t*)(smem + F2_KL + bro + 16);
                mma_bf16(sacc[ng], ah, bh2);
                mma_bf16(sacc[ng], ah, bl2);
                mma_bf16(sacc[ng], al, bh2);
            }
        }

        const int row0 = qb * 64 + wid * 16 + r4;
        if (kt == qb) {
            #pragma unroll
            for (int ng = 0; ng < 8; ng++) {
                int colb = kt * 64 + ng * 8 + k4 * 2;
                sacc[ng][0] = (colb     > row0)     ? -1e30f : sacc[ng][0] * scale;
                sacc[ng][1] = (colb + 1 > row0)     ? -1e30f : sacc[ng][1] * scale;
                sacc[ng][2] = (colb     > row0 + 8) ? -1e30f : sacc[ng][2] * scale;
                sacc[ng][3] = (colb + 1 > row0 + 8) ? -1e30f : sacc[ng][3] * scale;
            }
        } else {
            #pragma unroll
            for (int ng = 0; ng < 8; ng++)
                #pragma unroll
                for (int e = 0; e < 4; e++) sacc[ng][e] *= scale;
        }

        float mx0 = -1e30f, mx1 = -1e30f;
        #pragma unroll
        for (int ng = 0; ng < 8; ng++) {
            mx0 = fmaxf(mx0, fmaxf(sacc[ng][0], sacc[ng][1]));
            mx1 = fmaxf(mx1, fmaxf(sacc[ng][2], sacc[ng][3]));
        }
        mx0 = fmaxf(mx0, __shfl_xor_sync(0xffffffffu, mx0, 1));
        mx0 = fmaxf(mx0, __shfl_xor_sync(0xffffffffu, mx0, 2));
        mx1 = fmaxf(mx1, __shfl_xor_sync(0xffffffffu, mx1, 1));
        mx1 = fmaxf(mx1, __shfl_xor_sync(0xffffffffu, mx1, 2));

        float mn0 = fmaxf(m0, mx0), mn1 = fmaxf(m1, mx1);
        float c0 = __expf(m0 - mn0), c1 = __expf(m1 - mn1);
        m0 = mn0; m1 = mn1;

        float sum0 = 0.f, sum1 = 0.f;
        uint32_t ph2[8][2], pl2[8][2];
        #pragma unroll
        for (int ng = 0; ng < 8; ng++) {
            float p0 = __expf(sacc[ng][0] - m0);
            float p1 = __expf(sacc[ng][1] - m0);
            float p2 = __expf(sacc[ng][2] - m1);
            float p3 = __expf(sacc[ng][3] - m1);
            sum0 += p0 + p1; sum1 += p2 + p3;
            __nv_bfloat16 a, bq, cc, dd2, la, lb, lc, ld;
            split2(p0, a, la); split2(p1, bq, lb);
            split2(p2, cc, lc); split2(p3, dd2, ld);
            ph2[ng][0] = packbf(a, bq);  ph2[ng][1] = packbf(cc, dd2);
            pl2[ng][0] = packbf(la, lb); pl2[ng][1] = packbf(lc, ld);
        }
        sum0 += __shfl_xor_sync(0xffffffffu, sum0, 1);
        sum0 += __shfl_xor_sync(0xffffffffu, sum0, 2);
        sum1 += __shfl_xor_sync(0xffffffffu, sum1, 1);
        sum1 += __shfl_xor_sync(0xffffffffu, sum1, 2);
        l0 = l0 * c0 + sum0;
        l1 = l1 * c1 + sum1;

        #pragma unroll
        for (int n = 0; n < 16; n++) {
            oacc[n][0] *= c0; oacc[n][1] *= c0;
            oacc[n][2] *= c1; oacc[n][3] *= c1;
        }

        #pragma unroll
        for (int kb = 0; kb < 4; kb++) {
            uint32_t pa[4] = {ph2[2*kb][0], ph2[2*kb][1], ph2[2*kb+1][0], ph2[2*kb+1][1]};
            uint32_t pb[4] = {pl2[2*kb][0], pl2[2*kb][1], pl2[2*kb+1][0], pl2[2*kb+1][1]};
            const uint32_t koff = kb * 32 + k4 * 4;
            #pragma unroll
            for (int ng = 0; ng < 16; ng++) {
                const uint32_t vro = (ng * 8 + r4) * VROW + koff;
                uint32_t vh[2], vl[2];
                vh[0] = *(const uint32_t*)(smem + F2_VH + vro);
                vh[1] = *(const uint32_t*)(smem + F2_VH + vro + 16);
                vl[0] = *(const uint32_t*)(smem + F2_VL + vro);
                vl[1] = *(const uint32_t*)(smem + F2_VL + vro + 16);
                mma_bf16(oacc[ng], pa, vh);
                mma_bf16(oacc[ng], pa, vl);
                mma_bf16(oacc[ng], pb, vh);
            }
        }
    }

    const float inv0 = 1.0f / l0, inv1 = 1.0f / l1;
    const int grow0 = b * SS + qb * 64 + wid * 16 + r4;
    #pragma unroll
    for (int ng = 0; ng < 16; ng++) {
        size_t o0 = (size_t)grow0 * DD + h * DHH + ng * 8 + k4 * 2;
        size_t o1 = o0 + (size_t)8 * DD;
        float v0 = oacc[ng][0] * inv0, v1 = oacc[ng][1] * inv0;
        float v2 = oacc[ng][2] * inv1, v3 = oacc[ng][3] * inv1;
        __nv_bfloat16 h0, l0b, h1, l1b, h2, l2b, h3, l3b;
        split2(v0, h0, l0b); split2(v1, h1, l1b);
        split2(v2, h2, l2b); split2(v3, h3, l3b);
        *(uint32_t*)(attn_hi + o0) = packbf(h0, h1);
        *(uint32_t*)(attn_lo + o0) = packbf(l0b, l1b);
        *(uint32_t*)(attn_hi + o1) = packbf(h2, h3);
        *(uint32_t*)(attn_lo + o1) = packbf(l2b, l3b);
    }
}

// ---------------------------------------------------------------------------
// kernel_launch: inputs = [positions, hidden_states, w_qkv, w_out]
// ---------------------------------------------------------------------------
extern "C" void kernel_launch(void* const* d_in, const int* in_sizes, int n_in,
                              void* d_out, int out_size) {
    const float* hidden = (const float*)d_in[1];
    const float* w_qkv  = (const float*)d_in[2];
    const float* w_out  = (const float*)d_in[3];
    float* out = (float*)d_out;

    __nv_bfloat16 *xh, *xl, *wqh, *wql, *woh, *wol, *ah, *al;
    __nv_bfloat16 *qh, *ql, *kh, *kl, *vth, *vtl;
    float* qkv;
    cudaGetSymbolAddress((void**)&xh,  g_xln_hi);
    cudaGetSymbolAddress((void**)&xl,  g_xln_lo);
    cudaGetSymbolAddress((void**)&qkv, g_qkv);
    cudaGetSymbolAddress((void**)&wqh, g_wqkvT_hi);
    cudaGetSymbolAddress((void**)&wql, g_wqkvT_lo);
    cudaGetSymbolAddress((void**)&woh, g_woutT_hi);
    cudaGetSymbolAddress((void**)&wol, g_woutT_lo);
    cudaGetSymbolAddress((void**)&ah,  g_attn_hi);
    cudaGetSymbolAddress((void**)&al,  g_attn_lo);
    cudaGetSymbolAddress((void**)&qh,  g_qh);
    cudaGetSymbolAddress((void**)&ql,  g_ql);
    cudaGetSymbolAddress((void**)&kh,  g_kh);
    cudaGetSymbolAddress((void**)&kl,  g_kl);
    cudaGetSymbolAddress((void**)&vth, g_vth);
    cudaGetSymbolAddress((void**)&vtl, g_vtl);

    // 1) LayerNorm -> split bf16
    ln_kernel<<<NTOK, 256>>>(hidden, xh, xl);

    // 2) Weight transpose+split
    dim3 tb(32, 8);
    transpose_split<<<dim3(QKV_N / 32, DD / 32), tb>>>(w_qkv, wqh, wql, DD, QKV_N);
    transpose_split<<<dim3(DD / 32, DD / 32), tb>>>(w_out, woh, wol, DD, DD);

    // 3) QKV projection (tensor cores via mma.sync)
    cudaFuncSetAttribute(gemm_mma, cudaFuncAttributeMaxDynamicSharedMemorySize, GEMM_SMEM);
    gemm_mma<<<dim3(QKV_N / BN, NTOK / BM), 256, GEMM_SMEM>>>(
        xh, xl, wqh, wql, qkv, NTOK, QKV_N, DD);

    // 4) RoPE + split Q,K; transpose + split V
    rope_split<<<NTOK, 256>>>(qkv, qh, ql, kh, kl);
    v_split_transpose<<<dim3(SS / 64, HH, BB), 256>>>(qkv, vth, vtl);

    // 5) Causal flash attention v3 (pre-split operands) -> split bf16
    cudaFuncSetAttribute(flash3_kernel, cudaFuncAttributeMaxDynamicSharedMemorySize,
                         FLASH2_SMEM);
    flash3_kernel<<<dim3(SS / 64, HH, BB), 128, FLASH2_SMEM>>>(
        qh, ql, kh, kl, vth, vtl, ah, al);

    // 6) Output projection (tensor cores via mma.sync)
    gemm_mma<<<dim3(DD / BN, NTOK / BM), 256, GEMM_SMEM>>>(
        ah, al, woh, wol, out, NTOK, DD, DD);
}